// round 13
// baseline (speedup 1.0000x reference)
#include <cuda_runtime.h>
#include <math.h>
#include <stdint.h>

#define T_LEN 256
#define BB 64
#define SENT_D 320
#define UU 512
#define G4 2048
#define HD 1024
#define MTOT (T_LEN * BB)          // 16384
#define NCTA 128

typedef unsigned long long ull;

// ---------------- packed f32x2 + cp.async helpers ----------------------------
__device__ __forceinline__ void fma2(ull& d, ull a, ull b) {
    asm("fma.rn.f32x2 %0, %1, %2, %0;" : "+l"(d) : "l"(a), "l"(b));
}
__device__ __forceinline__ ull dup2(float x) {
    ull r;
    asm("mov.b64 %0, {%1, %1};" : "=l"(r) : "f"(x));
    return r;
}
__device__ __forceinline__ float2 unpack2(ull v) {
    float2 r;
    asm("mov.b64 {%0, %1}, %2;" : "=f"(r.x), "=f"(r.y) : "l"(v));
    return r;
}
__device__ __forceinline__ void cp_async16(uint32_t saddr, const void* gptr) {
    asm volatile("cp.async.cg.shared.global [%0], [%1], 16;" :: "r"(saddr), "l"(gptr));
}
__device__ __forceinline__ void cp_commit() {
    asm volatile("cp.async.commit_group;" ::: "memory");
}
template<int N> __device__ __forceinline__ void cp_wait() {
    asm volatile("cp.async.wait_group %0;" :: "n"(N) : "memory");
}

// ---------------- scratch (device globals; no allocs allowed) ----------------
__device__ float g_sent[MTOT * SENT_D];
__device__ float g_sentT[SENT_D * MTOT];
__device__ float g_preF[(size_t)MTOT * G4];
__device__ float g_preB[(size_t)MTOT * G4];
__device__ float g_in2[(size_t)MTOT * 1024];
__device__ float g_in2T[(size_t)1024 * MTOT];
__device__ float g_fwd2[(size_t)MTOT * UU];
__device__ float g_back2[(size_t)MTOT * UU];

__device__ float g_Wx1f[SENT_D * G4], g_Wx1b[SENT_D * G4];
__device__ float g_Wh1f[UU * G4],     g_Wh1b[UU * G4];   // k-paired + plane layout
__device__ float g_Wx2f[1024 * G4],   g_Wx2b[1024 * G4];
__device__ float g_Wh2f[UU * G4],     g_Wh2b[UU * G4];
__device__ float g_bv1f[G4], g_bv1b[G4], g_bv2f[G4], g_bv2b[G4];

__device__ float g_hFa[BB * UU], g_hFb[BB * UU];
__device__ float g_hBa[BB * UU], g_hBb[BB * UU];

__device__ float g_hi_s[BB * 8192];
__device__ float g_hi_l[BB * 6144];
__device__ float g_part_s[16 * BB * HD];
__device__ float g_part_l[12 * BB * HD];
__device__ float g_hs[BB * HD], g_hl[BB * HD];

// Dataflow flags: g_flag[dir][g] counts CTAs of k-group g (16 CTAs each,
// units k in [128g, 128g+128)) that finished epilogue. Monotonic: value
// 16*(s+1) after all produce h(s+1).
__device__ unsigned g_flag[2][4];

__device__ __forceinline__ void poll_flag(const unsigned* f, unsigned target) {
    unsigned x;
    do {
        asm volatile("ld.acquire.gpu.u32 %0, [%1];" : "=r"(x) : "l"(f) : "memory");
    } while (x < target);
}

// ---------------- weight packing ----------------------------------------------
// Wx: column n = u*4 + k. Wh: k-paired + per-32-gate-tile plane layout.
__global__ void pack_lstm(const float* __restrict__ W, const float* __restrict__ b,
                          float* __restrict__ Wx, float* __restrict__ Wh,
                          float* __restrict__ bv, int din) {
    int total = 4 * (din + UU) * UU;
    int stride = gridDim.x * blockDim.x;
    for (int idx = blockIdx.x * blockDim.x + threadIdx.x; idx < total; idx += stride) {
        int k = idx / ((din + UU) * UU);
        int rem = idx - k * ((din + UU) * UU);
        int d = rem / UU;
        int u = rem - d * UU;
        float v = W[idx];
        int n = u * 4 + k;
        if (d < din) {
            Wx[(size_t)d * G4 + n] = v;
        } else {
            int kd = d - din;
            int tile = n >> 5, loc = n & 31;
            int txx = loc >> 2, j = loc & 3;
            int col = tile * 64 + (j >> 1) * 32 + txx * 4 + ((j & 1) << 1) + (kd & 1);
            Wh[(size_t)(kd >> 1) * 4096 + col] = v;
        }
    }
    for (int i = blockIdx.x * blockDim.x + threadIdx.x; i < G4; i += stride) {
        int k = i & 3, u = i >> 2;
        bv[i] = b[k * UU + u];
    }
}

// ---------------- embedding gather + concat ----------------------------------
__global__ void embed_kernel(const float* __restrict__ we, const float* __restrict__ te,
                             const int* __restrict__ wi, const int* __restrict__ ti) {
    int idx = blockIdx.x * blockDim.x + threadIdx.x;
    int tb = idx / SENT_D;
    int j = idx - tb * SENT_D;
    float v;
    if (j < 256) v = we[(size_t)wi[tb] * 256 + j];
    else         v = te[(size_t)ti[tb] * 64 + (j - 256)];
    g_sent[idx] = v;
}

// ---------------- tiled transpose --------------------------------------------
__global__ void transpose32(const float* __restrict__ src, float* __restrict__ dst,
                            int R, int Cc) {
    __shared__ float tl[32][33];
    int c0 = blockIdx.x * 32, r0 = blockIdx.y * 32;
    int tx = threadIdx.x, ty = threadIdx.y;   // 32 x 8
#pragma unroll
    for (int i = 0; i < 32; i += 8)
        tl[ty + i][tx] = src[(size_t)(r0 + ty + i) * Cc + c0 + tx];
    __syncthreads();
#pragma unroll
    for (int i = 0; i < 32; i += 8)
        dst[(size_t)(c0 + ty + i) * R + r0 + tx] = tl[tx][ty + i];
}

// ---------------- LSTM h-state init + flag reset -------------------------------
__global__ void init_states(const float* __restrict__ c0f, const float* __restrict__ c0b) {
    int idx = blockIdx.x * blockDim.x + threadIdx.x;   // B*U = 32768
    if (idx < 8) ((unsigned*)g_flag)[idx] = 0;
    int u = idx & (UU - 1);
    g_hFa[idx] = tanhf(c0f[u]);
    g_hBa[idx] = tanhf(c0b[u]);
}

// ---------------- big GEMM: C = AT^T @ B, cp.async double-buffered ------------
__global__ void __launch_bounds__(256) sgemm_nt(
    const float* __restrict__ AT, const float* __restrict__ B, float* __restrict__ C,
    int K, int ldat, int ldb, int ldc) {
    __shared__ float As[2][16 * 132];
    __shared__ float Bs[2][16 * 132];
    int m0 = blockIdx.y * 128, n0 = blockIdx.x * 128;
    int tid = threadIdx.x;
    int tx = tid & 15, ty = tid >> 4;
    uint32_t as0 = (uint32_t)__cvta_generic_to_shared(&As[0][0]);
    uint32_t bs0 = (uint32_t)__cvta_generic_to_shared(&Bs[0][0]);
    int akk = tid >> 5, aoff = (tid & 31) * 4;

    ull acc[4][8];
#pragma unroll
    for (int p = 0; p < 4; p++)
#pragma unroll
        for (int j = 0; j < 8; j++) acc[p][j] = 0ULL;

#define SG_STAGE(pp, kk0) do { \
        cp_async16(as0 + (uint32_t)(((pp) * 2112 + akk * 132 + aoff) * 4), \
                   AT + (size_t)((kk0) + akk) * ldat + m0 + aoff); \
        cp_async16(as0 + (uint32_t)(((pp) * 2112 + (akk + 8) * 132 + aoff) * 4), \
                   AT + (size_t)((kk0) + akk + 8) * ldat + m0 + aoff); \
        cp_async16(bs0 + (uint32_t)(((pp) * 2112 + akk * 132 + aoff) * 4), \
                   B + (size_t)((kk0) + akk) * ldb + n0 + aoff); \
        cp_async16(bs0 + (uint32_t)(((pp) * 2112 + (akk + 8) * 132 + aoff) * 4), \
                   B + (size_t)((kk0) + akk + 8) * ldb + n0 + aoff); \
    } while (0)

    SG_STAGE(0, 0);
    cp_commit();

    int p = 0;
    for (int k0 = 0; k0 < K; k0 += 16, p ^= 1) {
        if (k0 + 16 < K) {
            SG_STAGE(p ^ 1, k0 + 16);
            cp_commit();
            cp_wait<1>();
        } else {
            cp_wait<0>();
        }
        __syncthreads();
        const float* Ap = &As[p][0];
        const float* Bp = &Bs[p][0];
#pragma unroll
        for (int kk = 0; kk < 16; kk++) {
            ull ap[4];
#pragma unroll
            for (int q = 0; q < 4; q++)
                ap[q] = *(const ull*)(Ap + kk * 132 + ty * 8 + 2 * q);
            float4 bv0 = *(const float4*)(Bp + kk * 132 + tx * 8);
            float4 bv1 = *(const float4*)(Bp + kk * 132 + tx * 8 + 4);
            ull bd[8] = {dup2(bv0.x), dup2(bv0.y), dup2(bv0.z), dup2(bv0.w),
                         dup2(bv1.x), dup2(bv1.y), dup2(bv1.z), dup2(bv1.w)};
#pragma unroll
            for (int q = 0; q < 4; q++)
#pragma unroll
                for (int j = 0; j < 8; j++) fma2(acc[q][j], ap[q], bd[j]);
        }
        __syncthreads();
    }
#undef SG_STAGE

#pragma unroll
    for (int q = 0; q < 4; q++) {
        float v0[8], v1[8];
#pragma unroll
        for (int j = 0; j < 8; j++) {
            float2 t = unpack2(acc[q][j]);
            v0[j] = t.x; v1[j] = t.y;
        }
        float* c0 = C + (size_t)(m0 + ty * 8 + 2 * q) * ldc + n0 + tx * 8;
        float* c1 = c0 + ldc;
        *(float4*)c0 = make_float4(v0[0], v0[1], v0[2], v0[3]);
        *(float4*)(c0 + 4) = make_float4(v0[4], v0[5], v0[6], v0[7]);
        *(float4*)c1 = make_float4(v1[0], v1[1], v1[2], v1[3]);
        *(float4*)(c1 + 4) = make_float4(v1[4], v1[5], v1[6], v1[7]);
    }
}

// ---------------- fused recurrence layer: dataflow-synchronized ---------------
// 128 CTAs x 128 thr; blk>>6 = dir, blk&63 = 32-wide gate tile. Thread tile
// 4b x 4g. W resident in smem; A staged via 4-stage cp.async ring; c in regs.
// Cross-CTA sync: per-k-group monotonic flags (NO full grid barrier). Stage i
// of step s polls flag[dir][i>>2] >= 16*s just before staging; the 3-stage
// prefetch distance gives later k-group producers free slack. WAR is safe
// inductively: own polls during k-loop(s) prove all peers completed
// k-loop(s-1) reads before h(s+1) overwrites that buffer.
__global__ void __launch_bounds__(128) lstm_layer(
    const float* __restrict__ preF, const float* __restrict__ preB,
    const float* __restrict__ WpF,  const float* __restrict__ WpB,
    const float* __restrict__ bvF,  const float* __restrict__ bvB,
    const float* __restrict__ c0F,  const float* __restrict__ c0B,
    float* __restrict__ outF, float* __restrict__ outB,
    float* __restrict__ outTF, float* __restrict__ outTB, int ostride) {
    extern __shared__ float sm[];
    float* Wsm = sm;                    // 16384 floats (resident W slice)
    float* Asm = sm + 16384;            // 4 stages x 2304 floats

    int blk = blockIdx.x;
    int dir = blk >> 6;
    int nb  = blk & 63;
    int n0  = nb * 32;

    const float* pre = dir ? preB : preF;
    const float* Wp  = dir ? WpB : WpF;
    const float* bv  = dir ? bvB : bvF;
    const float* c0p = dir ? c0B : c0F;
    float* outp  = dir ? outB : outF;
    float* outT  = dir ? outTB : outTF;
    float* hbuf0 = dir ? g_hBa : g_hFa;
    float* hbuf1 = dir ? g_hBb : g_hFb;
    unsigned* flags = g_flag[dir];
    unsigned* myflag = &g_flag[dir][nb >> 4];

    int tid = threadIdx.x;
    int tx = tid >> 4;            // 0..7 : unit within tile
    int ty = tid & 15;            // 0..15: b-group of 4
    int b0 = ty * 4;
    int u = nb * 8 + tx;

    uint32_t wsb = (uint32_t)__cvta_generic_to_shared(Wsm);
    uint32_t asb = (uint32_t)__cvta_generic_to_shared(Asm);

    // load resident W slice: each thread fills its contiguous 128-float span
#pragma unroll
    for (int j = 0; j < 32; j++) {
        int f = tid * 128 + j * 4;
        int row = f >> 6, col = f & 63;
        cp_async16(wsb + (uint32_t)f * 4, Wp + (size_t)row * 4096 + nb * 64 + col);
    }
    cp_commit();

    float4 bb4 = *(const float4*)(bv + n0 + tx * 4);
    float c0v = c0p[u];
    float cv[4] = {c0v, c0v, c0v, c0v};

    // A staging assignment: permuted rows, stride 36
    int sa_row = tid >> 1, sa_off = (tid & 1) * 16;
    int sa_prow = (sa_row & 3) * 16 + (sa_row >> 2);

    cp_wait<0>();
    __syncthreads();   // W resident ready

#define LSA(st, k0) do { \
        _Pragma("unroll") \
        for (int j = 0; j < 4; j++) \
            cp_async16(asb + (uint32_t)((((st) * 2304) + sa_prow * 36 + sa_off + j * 4) * 4), \
                       hin + sa_row * UU + (k0) + sa_off + j * 4); \
    } while (0)

    for (int s = 0; s < T_LEN; s++) {
        int t = dir ? (T_LEN - 1 - s) : s;
        const float* hin = (s & 1) ? hbuf1 : hbuf0;
        float* hout      = (s & 1) ? hbuf0 : hbuf1;
        unsigned ftarget = 16u * (unsigned)s;

        // per-step pre loads (latency hides under staging + k-loop)
        float4 pv[4];
#pragma unroll
        for (int r = 0; r < 4; r++)
            pv[r] = *(const float4*)(pre + ((size_t)t * BB + b0 + r) * G4 + n0 + tx * 4);

        poll_flag(&flags[0], ftarget);   // stages 0..3 (k 0..127)
        LSA(0, 0);  cp_commit();
        LSA(1, 32); cp_commit();
        LSA(2, 64); cp_commit();

        ull acc[4][4];
#pragma unroll
        for (int r = 0; r < 4; r++)
#pragma unroll
            for (int j = 0; j < 4; j++) acc[r][j] = 0ULL;

        for (int i = 0; i < 16; i++) {
            if (i < 13)      cp_wait<2>();
            else if (i < 15) cp_wait<1>();
            else             cp_wait<0>();
            __syncthreads();
            const float* Ap = Asm + (i & 3) * 2304;
            const float* Bp = Wsm + i * 1024;
#pragma unroll
            for (int kk4 = 0; kk4 < 8; kk4++) {
                ulonglong2 a2[4];
#pragma unroll
                for (int r = 0; r < 4; r++)
                    a2[r] = *(const ulonglong2*)(Ap + (r * 16 + ty) * 36 + kk4 * 4);
#pragma unroll
                for (int h = 0; h < 2; h++) {
                    int kk2 = kk4 * 2 + h;
                    ulonglong2 w01 = *(const ulonglong2*)(Bp + kk2 * 64 + tx * 4);
                    ulonglong2 w23 = *(const ulonglong2*)(Bp + kk2 * 64 + 32 + tx * 4);
#pragma unroll
                    for (int r = 0; r < 4; r++) {
                        ull a = h ? a2[r].y : a2[r].x;
                        fma2(acc[r][0], a, w01.x);
                        fma2(acc[r][1], a, w01.y);
                        fma2(acc[r][2], a, w23.x);
                        fma2(acc[r][3], a, w23.y);
                    }
                }
            }
            if (i + 3 < 16) {
                if (((i + 3) & 3) == 0)            // entering a new k-group
                    poll_flag(&flags[(i + 3) >> 2], ftarget);
                LSA((i + 3) & 3, (i + 3) * 32);
                cp_commit();
            }
        }

        // epilogue: gates + state update (c stays in registers)
#pragma unroll
        for (int r = 0; r < 4; r++) {
            int b = b0 + r;
            float2 e0 = unpack2(acc[r][0]);
            float2 e1 = unpack2(acc[r][1]);
            float2 e2 = unpack2(acc[r][2]);
            float2 e3 = unpack2(acc[r][3]);
            float gi = e0.x + e0.y + pv[r].x + bb4.x;
            float gf = e1.x + e1.y + pv[r].y + bb4.y;
            float go = e2.x + e2.y + pv[r].z + bb4.z;
            float gg = e3.x + e3.y + pv[r].w + bb4.w;
            float ig = 1.f / (1.f + expf(-gi));
            float fg = 1.f / (1.f + expf(-gf));
            float og = 1.f / (1.f + expf(-go));
            float gt = tanhf(gg);
            float c = fg * cv[r] + ig * gt;
            float h = og * tanhf(c);
            cv[r] = c;
            hout[b * UU + u] = h;
            outp[((size_t)t * BB + b) * ostride + u] = h;
            if (outT) outT[(size_t)u * MTOT + t * BB + b] = h;
        }

        // publish: drain h stores to L2, then bump this CTA's group flag
        __syncthreads();
        asm volatile("fence.acq_rel.gpu;" ::: "memory");
        if (tid == 0)
            asm volatile("red.release.gpu.add.u32 [%0], 1;" :: "l"(myflag) : "memory");
    }
#undef LSA
}

// ---------------- span feature gather ----------------------------------------
__global__ void build_hi(const int* __restrict__ sl, const int* __restrict__ sr,
                         const int* __restrict__ ll, const int* __restrict__ lr) {
    int idx = blockIdx.x * blockDim.x + threadIdx.x;
    const int NS = BB * 4 * 2048;
    int b, s, c, le, ri;
    float* dst;
    if (idx < NS) {
        b = idx / (4 * 2048); int r = idx - b * (4 * 2048);
        s = r / 2048; c = r - s * 2048;
        le = sl[b * 4 + s]; ri = sr[b * 4 + s];
        dst = g_hi_s + (size_t)b * 8192 + s * 2048 + c;
    } else {
        int j = idx - NS;
        b = j / (3 * 2048); int r = j - b * (3 * 2048);
        s = r / 2048; c = r - s * 2048;
        le = ll[b * 3 + s]; ri = lr[b * 3 + s];
        dst = g_hi_l + (size_t)b * 6144 + s * 2048 + c;
    }
    float v;
    if (c < 512) {
        v = g_in2[((size_t)ri * BB + b) * 1024 + c] - g_in2[((size_t)(le - 1) * BB + b) * 1024 + c];
    } else if (c < 1024) {
        int u = c - 512;
        v = g_fwd2[((size_t)ri * BB + b) * UU + u] - g_fwd2[((size_t)(le - 1) * BB + b) * UU + u];
    } else if (c < 1536) {
        int u = c - 1024;
        v = g_in2[((size_t)le * BB + b) * 1024 + 512 + u] - g_in2[((size_t)(ri + 1) * BB + b) * 1024 + 512 + u];
    } else {
        int u = c - 1536;
        v = g_back2[((size_t)le * BB + b) * UU + u] - g_back2[((size_t)(ri + 1) * BB + b) * UU + u];
    }
    *dst = v;
}

// ---------------- span hidden GEMM: M=64, split-K -----------------------------
__global__ void __launch_bounds__(256) span_gemm(
    const float* __restrict__ A, int lda, const float* __restrict__ B,
    float* __restrict__ Cpart) {
    __shared__ float AsT[16][68];
    __shared__ float Bs[16][68];
    int n0 = blockIdx.x * 64;
    int kbase = blockIdx.y * 512;
    int tid = threadIdx.x;
    int tx = tid & 15, ty = tid >> 4;
    float acc[4][4] = {{0}};
    int ab = tid >> 2, aseg = (tid & 3) * 4;
    int bkk = tid >> 4, bnn = (tid & 15) * 4;
    for (int k0 = kbase; k0 < kbase + 512; k0 += 16) {
        float4 av = *(const float4*)(A + (size_t)ab * lda + k0 + aseg);
        float4 wv = *(const float4*)(B + (size_t)(k0 + bkk) * HD + n0 + bnn);
        __syncthreads();
        AsT[aseg + 0][ab] = av.x; AsT[aseg + 1][ab] = av.y;
        AsT[aseg + 2][ab] = av.z; AsT[aseg + 3][ab] = av.w;
        *(float4*)&Bs[bkk][bnn] = wv;
        __syncthreads();
#pragma unroll
        for (int kk = 0; kk < 16; kk++) {
            float4 a = *(float4*)&AsT[kk][ty * 4];
            float4 w = *(float4*)&Bs[kk][tx * 4];
            float aa[4] = {a.x, a.y, a.z, a.w};
            float ww[4] = {w.x, w.y, w.z, w.w};
#pragma unroll
            for (int i = 0; i < 4; i++)
#pragma unroll
                for (int j = 0; j < 4; j++) acc[i][j] += aa[i] * ww[j];
        }
    }
#pragma unroll
    for (int i = 0; i < 4; i++) {
        int b = ty * 4 + i;
        float4 v = {acc[i][0], acc[i][1], acc[i][2], acc[i][3]};
        *(float4*)(Cpart + ((size_t)blockIdx.y * BB + b) * HD + n0 + tx * 4) = v;
    }
}

__global__ void reduce_relu(const float* __restrict__ part, int nch,
                            const float* __restrict__ bias, float* __restrict__ outh) {
    int idx = blockIdx.x * blockDim.x + threadIdx.x;
    int n = idx & (HD - 1);
    float s = bias[n];
    for (int ch = 0; ch < nch; ch++) s += part[(size_t)ch * BB * HD + idx];
    outh[idx] = fmaxf(s, 0.f);
}

// ---------------- output heads ------------------------------------------------
__global__ void out_heads(const float* __restrict__ soW, const float* __restrict__ sob,
                          const float* __restrict__ loW, const float* __restrict__ lob,
                          float* __restrict__ out) {
    __shared__ float s1[HD], s2[HD];
    int b = blockIdx.x, tid = threadIdx.x;
    for (int i = tid; i < HD; i += blockDim.x) {
        s1[i] = g_hs[b * HD + i];
        s2[i] = g_hl[b * HD + i];
    }
    __syncthreads();
    if (tid < 2) {
        float s = sob[tid];
        for (int k = 0; k < HD; k++) s += s1[k] * soW[k * 2 + tid];
        out[b * 2 + tid] = s;
    } else if (tid < 34) {
        int j = tid - 2;
        float s = lob[j];
        for (int k = 0; k < HD; k++) s += s2[k] * loW[k * 32 + j];
        out[128 + b * 32 + j] = s;
    }
}

// ---------------- host driver --------------------------------------------------
static float* sym(const void* symbol) {
    void* p = nullptr;
    cudaGetSymbolAddress(&p, symbol);
    return (float*)p;
}

extern "C" void kernel_launch(void* const* d_in, const int* in_sizes, int n_in,
                              void* d_out, int out_size) {
    const float* word_emb = (const float*)d_in[0];
    const float* tag_emb  = (const float*)d_in[1];
    const float* l1f_W = (const float*)d_in[2];
    const float* l1f_b = (const float*)d_in[3];
    const float* l1f_c0 = (const float*)d_in[4];
    const float* l1b_W = (const float*)d_in[5];
    const float* l1b_b = (const float*)d_in[6];
    const float* l1b_c0 = (const float*)d_in[7];
    const float* l2f_W = (const float*)d_in[8];
    const float* l2f_b = (const float*)d_in[9];
    const float* l2f_c0 = (const float*)d_in[10];
    const float* l2b_W = (const float*)d_in[11];
    const float* l2b_b = (const float*)d_in[12];
    const float* l2b_c0 = (const float*)d_in[13];
    const float* sh_W = (const float*)d_in[14];
    const float* sh_b = (const float*)d_in[15];
    const float* so_W = (const float*)d_in[16];
    const float* so_b = (const float*)d_in[17];
    const float* lh_W = (const float*)d_in[18];
    const float* lh_b = (const float*)d_in[19];
    const float* lo_W = (const float*)d_in[20];
    const float* lo_b = (const float*)d_in[21];
    const int* word_inds = (const int*)d_in[22];
    const int* tag_inds  = (const int*)d_in[23];
    const int* s_lefts  = (const int*)d_in[24];
    const int* s_rights = (const int*)d_in[25];
    const int* l_lefts  = (const int*)d_in[26];
    const int* l_rights = (const int*)d_in[27];
    float* out = (float*)d_out;

    float* p_sent  = sym(g_sent);
    float* p_sentT = sym(g_sentT);
    float* p_preF  = sym(g_preF);
    float* p_preB  = sym(g_preB);
    float* p_in2   = sym(g_in2);
    float* p_in2T  = sym(g_in2T);
    float* p_fwd2  = sym(g_fwd2);
    float* p_back2 = sym(g_back2);
    float* p_Wx1f = sym(g_Wx1f); float* p_Wx1b = sym(g_Wx1b);
    float* p_Wh1f = sym(g_Wh1f); float* p_Wh1b = sym(g_Wh1b);
    float* p_Wx2f = sym(g_Wx2f); float* p_Wx2b = sym(g_Wx2b);
    float* p_Wh2f = sym(g_Wh2f); float* p_Wh2b = sym(g_Wh2b);
    float* p_bv1f = sym(g_bv1f); float* p_bv1b = sym(g_bv1b);
    float* p_bv2f = sym(g_bv2f); float* p_bv2b = sym(g_bv2b);
    float* p_hi_s = sym(g_hi_s); float* p_hi_l = sym(g_hi_l);
    float* p_part_s = sym(g_part_s); float* p_part_l = sym(g_part_l);
    float* p_hs = sym(g_hs); float* p_hl = sym(g_hl);

    const int LSTM_SMEM = (16384 + 4 * 2304) * 4;   // 102,400 B
    static int smem_set = 0;
    if (!smem_set) {
        cudaFuncSetAttribute(lstm_layer, cudaFuncAttributeMaxDynamicSharedMemorySize,
                             LSTM_SMEM);
        smem_set = 1;
    }

    // 1) pack weights
    pack_lstm<<<2048, 256>>>(l1f_W, l1f_b, p_Wx1f, p_Wh1f, p_bv1f, SENT_D);
    pack_lstm<<<2048, 256>>>(l1b_W, l1b_b, p_Wx1b, p_Wh1b, p_bv1b, SENT_D);
    pack_lstm<<<4096, 256>>>(l2f_W, l2f_b, p_Wx2f, p_Wh2f, p_bv2f, 1024);
    pack_lstm<<<4096, 256>>>(l2b_W, l2b_b, p_Wx2b, p_Wh2b, p_bv2b, 1024);

    // 2) embeddings + transpose for GEMM A operand
    embed_kernel<<<(MTOT * SENT_D) / 256, 256>>>(word_emb, tag_emb, word_inds, tag_inds);
    transpose32<<<dim3(SENT_D / 32, MTOT / 32), dim3(32, 8)>>>(p_sent, p_sentT, MTOT, SENT_D);

    // 3) layer-1 input projections (16384 x 320 x 2048)
    dim3 gpre(G4 / 128, MTOT / 128);
    sgemm_nt<<<gpre, 256>>>(p_sentT, p_Wx1f, p_preF, SENT_D, MTOT, G4, G4);
    sgemm_nt<<<gpre, 256>>>(p_sentT, p_Wx1b, p_preB, SENT_D, MTOT, G4, G4);

    // 4) layer-1 recurrence: ONE fused dataflow launch
    init_states<<<(BB * UU) / 256, 256>>>(l1f_c0, l1b_c0);
    lstm_layer<<<NCTA, 128, LSTM_SMEM>>>(
        p_preF, p_preB, p_Wh1f, p_Wh1b, p_bv1f, p_bv1b, l1f_c0, l1b_c0,
        p_in2, p_in2 + 512, p_in2T, p_in2T + (size_t)512 * MTOT, 1024);

    // 5) layer-2 input projections (16384 x 1024 x 2048)
    sgemm_nt<<<gpre, 256>>>(p_in2T, p_Wx2f, p_preF, 1024, MTOT, G4, G4);
    sgemm_nt<<<gpre, 256>>>(p_in2T, p_Wx2b, p_preB, 1024, MTOT, G4, G4);

    // 6) layer-2 recurrence
    init_states<<<(BB * UU) / 256, 256>>>(l2f_c0, l2b_c0);
    lstm_layer<<<NCTA, 128, LSTM_SMEM>>>(
        p_preF, p_preB, p_Wh2f, p_Wh2b, p_bv2f, p_bv2b, l2f_c0, l2b_c0,
        p_fwd2, p_back2, (float*)nullptr, (float*)nullptr, UU);

    // 7) span features
    build_hi<<<(BB * 7 * 2048) / 256, 256>>>(s_lefts, s_rights, l_lefts, l_rights);

    // 8) span hidden layers
    span_gemm<<<dim3(HD / 64, 16), 256>>>(p_hi_s, 8192, sh_W, p_part_s);
    span_gemm<<<dim3(HD / 64, 12), 256>>>(p_hi_l, 6144, lh_W, p_part_l);
    reduce_relu<<<(BB * HD) / 256, 256>>>(p_part_s, 16, sh_b, p_hs);
    reduce_relu<<<(BB * HD) / 256, 256>>>(p_part_l, 12, lh_b, p_hl);

    // 9) output heads
    out_heads<<<BB, 128>>>(so_W, so_b, lo_W, lo_b, out);
}

// round 14
// speedup vs baseline: 1.2491x; 1.2491x over previous
#include <cuda_runtime.h>
#include <math.h>
#include <stdint.h>

#define T_LEN 256
#define BB 64
#define SENT_D 320
#define UU 512
#define G4 2048
#define HD 1024
#define MTOT (T_LEN * BB)          // 16384
#define NCTA 128

typedef unsigned long long ull;

// ---------------- packed f32x2 + cp.async helpers ----------------------------
__device__ __forceinline__ void fma2(ull& d, ull a, ull b) {
    asm("fma.rn.f32x2 %0, %1, %2, %0;" : "+l"(d) : "l"(a), "l"(b));
}
__device__ __forceinline__ ull dup2(float x) {
    ull r;
    asm("mov.b64 %0, {%1, %1};" : "=l"(r) : "f"(x));
    return r;
}
__device__ __forceinline__ float2 unpack2(ull v) {
    float2 r;
    asm("mov.b64 {%0, %1}, %2;" : "=f"(r.x), "=f"(r.y) : "l"(v));
    return r;
}
__device__ __forceinline__ void cp_async16(uint32_t saddr, const void* gptr) {
    asm volatile("cp.async.cg.shared.global [%0], [%1], 16;" :: "r"(saddr), "l"(gptr));
}
__device__ __forceinline__ void cp_commit() {
    asm volatile("cp.async.commit_group;" ::: "memory");
}
template<int N> __device__ __forceinline__ void cp_wait() {
    asm volatile("cp.async.wait_group %0;" :: "n"(N) : "memory");
}

// ---------------- scratch (device globals; no allocs allowed) ----------------
__device__ float g_sent[MTOT * SENT_D];
__device__ float g_sentT[SENT_D * MTOT];
__device__ float g_preF[(size_t)MTOT * G4];
__device__ float g_preB[(size_t)MTOT * G4];
__device__ float g_in2[(size_t)MTOT * 1024];
__device__ float g_in2T[(size_t)1024 * MTOT];
__device__ float g_fwd2[(size_t)MTOT * UU];
__device__ float g_back2[(size_t)MTOT * UU];

__device__ float g_Wx1f[SENT_D * G4], g_Wx1b[SENT_D * G4];
__device__ float g_Wh1f[UU * G4],     g_Wh1b[UU * G4];   // k-paired + plane layout
__device__ float g_Wx2f[1024 * G4],   g_Wx2b[1024 * G4];
__device__ float g_Wh2f[UU * G4],     g_Wh2b[UU * G4];
__device__ float g_bv1f[G4], g_bv1b[G4], g_bv2f[G4], g_bv2b[G4];

__device__ float g_hFa[BB * UU], g_hFb[BB * UU];
__device__ float g_hBa[BB * UU], g_hBb[BB * UU];

__device__ float g_hi_s[BB * 8192];
__device__ float g_hi_l[BB * 6144];
__device__ float g_part_s[16 * BB * HD];
__device__ float g_part_l[12 * BB * HD];
__device__ float g_hs[BB * HD], g_hl[BB * HD];

// one monotonic barrier counter per direction (64 CTAs each; padded lines)
__device__ unsigned g_sc[2][32];

// Per-direction grid barrier: each thread drains its own STG writes to the
// gpu coherence point BEFORE arriving, then t0 does release-add+acquire-poll.
__device__ __forceinline__ void gbar(unsigned* ctr, unsigned target) {
    __syncthreads();
    asm volatile("fence.acq_rel.gpu;" ::: "memory");
    if (threadIdx.x == 0) {
        asm volatile("red.release.gpu.add.u32 [%0], 1;" :: "l"(ctr) : "memory");
        unsigned x;
        do {
            asm volatile("ld.acquire.gpu.u32 %0, [%1];" : "=r"(x) : "l"(ctr) : "memory");
        } while (x < target);
    }
    __syncthreads();
}

// ---------------- weight packing ----------------------------------------------
// Wx: column n = u*4 + k. Wh: k-paired + per-32-gate-tile plane layout.
__global__ void pack_lstm(const float* __restrict__ W, const float* __restrict__ b,
                          float* __restrict__ Wx, float* __restrict__ Wh,
                          float* __restrict__ bv, int din) {
    int total = 4 * (din + UU) * UU;
    int stride = gridDim.x * blockDim.x;
    for (int idx = blockIdx.x * blockDim.x + threadIdx.x; idx < total; idx += stride) {
        int k = idx / ((din + UU) * UU);
        int rem = idx - k * ((din + UU) * UU);
        int d = rem / UU;
        int u = rem - d * UU;
        float v = W[idx];
        int n = u * 4 + k;
        if (d < din) {
            Wx[(size_t)d * G4 + n] = v;
        } else {
            int kd = d - din;
            int tile = n >> 5, loc = n & 31;
            int txx = loc >> 2, j = loc & 3;
            int col = tile * 64 + (j >> 1) * 32 + txx * 4 + ((j & 1) << 1) + (kd & 1);
            Wh[(size_t)(kd >> 1) * 4096 + col] = v;
        }
    }
    for (int i = blockIdx.x * blockDim.x + threadIdx.x; i < G4; i += stride) {
        int k = i & 3, u = i >> 2;
        bv[i] = b[k * UU + u];
    }
}

// ---------------- embedding gather + concat ----------------------------------
__global__ void embed_kernel(const float* __restrict__ we, const float* __restrict__ te,
                             const int* __restrict__ wi, const int* __restrict__ ti) {
    int idx = blockIdx.x * blockDim.x + threadIdx.x;
    int tb = idx / SENT_D;
    int j = idx - tb * SENT_D;
    float v;
    if (j < 256) v = we[(size_t)wi[tb] * 256 + j];
    else         v = te[(size_t)ti[tb] * 64 + (j - 256)];
    g_sent[idx] = v;
}

// ---------------- tiled transpose --------------------------------------------
__global__ void transpose32(const float* __restrict__ src, float* __restrict__ dst,
                            int R, int Cc) {
    __shared__ float tl[32][33];
    int c0 = blockIdx.x * 32, r0 = blockIdx.y * 32;
    int tx = threadIdx.x, ty = threadIdx.y;   // 32 x 8
#pragma unroll
    for (int i = 0; i < 32; i += 8)
        tl[ty + i][tx] = src[(size_t)(r0 + ty + i) * Cc + c0 + tx];
    __syncthreads();
#pragma unroll
    for (int i = 0; i < 32; i += 8)
        dst[(size_t)(c0 + ty + i) * R + r0 + tx] = tl[tx][ty + i];
}

// ---------------- LSTM h-state init + barrier counter reset -------------------
__global__ void init_states(const float* __restrict__ c0f, const float* __restrict__ c0b) {
    int idx = blockIdx.x * blockDim.x + threadIdx.x;   // B*U = 32768
    if (idx < 2) g_sc[idx][0] = 0;
    int u = idx & (UU - 1);
    g_hFa[idx] = tanhf(c0f[u]);
    g_hBa[idx] = tanhf(c0b[u]);
}

// ---------------- big GEMM: C = AT^T @ B, cp.async double-buffered ------------
__global__ void __launch_bounds__(256) sgemm_nt(
    const float* __restrict__ AT, const float* __restrict__ B, float* __restrict__ C,
    int K, int ldat, int ldb, int ldc) {
    __shared__ float As[2][16 * 132];
    __shared__ float Bs[2][16 * 132];
    int m0 = blockIdx.y * 128, n0 = blockIdx.x * 128;
    int tid = threadIdx.x;
    int tx = tid & 15, ty = tid >> 4;
    uint32_t as0 = (uint32_t)__cvta_generic_to_shared(&As[0][0]);
    uint32_t bs0 = (uint32_t)__cvta_generic_to_shared(&Bs[0][0]);
    int akk = tid >> 5, aoff = (tid & 31) * 4;

    ull acc[4][8];
#pragma unroll
    for (int p = 0; p < 4; p++)
#pragma unroll
        for (int j = 0; j < 8; j++) acc[p][j] = 0ULL;

#define SG_STAGE(pp, kk0) do { \
        cp_async16(as0 + (uint32_t)(((pp) * 2112 + akk * 132 + aoff) * 4), \
                   AT + (size_t)((kk0) + akk) * ldat + m0 + aoff); \
        cp_async16(as0 + (uint32_t)(((pp) * 2112 + (akk + 8) * 132 + aoff) * 4), \
                   AT + (size_t)((kk0) + akk + 8) * ldat + m0 + aoff); \
        cp_async16(bs0 + (uint32_t)(((pp) * 2112 + akk * 132 + aoff) * 4), \
                   B + (size_t)((kk0) + akk) * ldb + n0 + aoff); \
        cp_async16(bs0 + (uint32_t)(((pp) * 2112 + (akk + 8) * 132 + aoff) * 4), \
                   B + (size_t)((kk0) + akk + 8) * ldb + n0 + aoff); \
    } while (0)

    SG_STAGE(0, 0);
    cp_commit();

    int p = 0;
    for (int k0 = 0; k0 < K; k0 += 16, p ^= 1) {
        if (k0 + 16 < K) {
            SG_STAGE(p ^ 1, k0 + 16);
            cp_commit();
            cp_wait<1>();
        } else {
            cp_wait<0>();
        }
        __syncthreads();
        const float* Ap = &As[p][0];
        const float* Bp = &Bs[p][0];
#pragma unroll
        for (int kk = 0; kk < 16; kk++) {
            ull ap[4];
#pragma unroll
            for (int q = 0; q < 4; q++)
                ap[q] = *(const ull*)(Ap + kk * 132 + ty * 8 + 2 * q);
            float4 bv0 = *(const float4*)(Bp + kk * 132 + tx * 8);
            float4 bv1 = *(const float4*)(Bp + kk * 132 + tx * 8 + 4);
            ull bd[8] = {dup2(bv0.x), dup2(bv0.y), dup2(bv0.z), dup2(bv0.w),
                         dup2(bv1.x), dup2(bv1.y), dup2(bv1.z), dup2(bv1.w)};
#pragma unroll
            for (int q = 0; q < 4; q++)
#pragma unroll
                for (int j = 0; j < 8; j++) fma2(acc[q][j], ap[q], bd[j]);
        }
        __syncthreads();
    }
#undef SG_STAGE

#pragma unroll
    for (int q = 0; q < 4; q++) {
        float v0[8], v1[8];
#pragma unroll
        for (int j = 0; j < 8; j++) {
            float2 t = unpack2(acc[q][j]);
            v0[j] = t.x; v1[j] = t.y;
        }
        float* c0 = C + (size_t)(m0 + ty * 8 + 2 * q) * ldc + n0 + tx * 8;
        float* c1 = c0 + ldc;
        *(float4*)c0 = make_float4(v0[0], v0[1], v0[2], v0[3]);
        *(float4*)(c0 + 4) = make_float4(v0[4], v0[5], v0[6], v0[7]);
        *(float4*)c1 = make_float4(v1[0], v1[1], v1[2], v1[3]);
        *(float4*)(c1 + 4) = make_float4(v1[4], v1[5], v1[6], v1[7]);
    }
}

// ---------------- fused recurrence layer: 128 CTAs x 128 thr, 1 launch --------
// R12 structure; sync via PER-DIRECTION barrier (64 CTAs each — F and B are
// independent chains), and next-step pre loads issued BEFORE the barrier so
// their latency hides under the wait.
__global__ void __launch_bounds__(128) lstm_layer(
    const float* __restrict__ preF, const float* __restrict__ preB,
    const float* __restrict__ WpF,  const float* __restrict__ WpB,
    const float* __restrict__ bvF,  const float* __restrict__ bvB,
    const float* __restrict__ c0F,  const float* __restrict__ c0B,
    float* __restrict__ outF, float* __restrict__ outB,
    float* __restrict__ outTF, float* __restrict__ outTB, int ostride) {
    extern __shared__ float sm[];
    float* Wsm = sm;                    // 16384 floats (resident W slice)
    float* Asm = sm + 16384;            // 4 stages x 2304 floats

    int blk = blockIdx.x;
    int dir = blk >> 6;
    int nb  = blk & 63;
    int n0  = nb * 32;

    const float* pre = dir ? preB : preF;
    const float* Wp  = dir ? WpB : WpF;
    const float* bv  = dir ? bvB : bvF;
    const float* c0p = dir ? c0B : c0F;
    float* outp  = dir ? outB : outF;
    float* outT  = dir ? outTB : outTF;
    float* hbuf0 = dir ? g_hBa : g_hFa;
    float* hbuf1 = dir ? g_hBb : g_hFb;
    unsigned* ctr = &g_sc[dir][0];

    int tid = threadIdx.x;
    int tx = tid >> 4;            // 0..7 : unit within tile
    int ty = tid & 15;            // 0..15: b-group of 4
    int b0 = ty * 4;
    int u = nb * 8 + tx;

    uint32_t wsb = (uint32_t)__cvta_generic_to_shared(Wsm);
    uint32_t asb = (uint32_t)__cvta_generic_to_shared(Asm);

    // load resident W slice: each thread fills its contiguous 128-float span
#pragma unroll
    for (int j = 0; j < 32; j++) {
        int f = tid * 128 + j * 4;
        int row = f >> 6, col = f & 63;
        cp_async16(wsb + (uint32_t)f * 4, Wp + (size_t)row * 4096 + nb * 64 + col);
    }
    cp_commit();

    float4 bb4 = *(const float4*)(bv + n0 + tx * 4);
    float c0v = c0p[u];
    float cv[4] = {c0v, c0v, c0v, c0v};

    // A staging assignment: permuted rows, stride 36
    int sa_row = tid >> 1, sa_off = (tid & 1) * 16;
    int sa_prow = (sa_row & 3) * 16 + (sa_row >> 2);

    cp_wait<0>();
    __syncthreads();   // W resident ready

#define LSA(st, k0) do { \
        _Pragma("unroll") \
        for (int j = 0; j < 4; j++) \
            cp_async16(asb + (uint32_t)((((st) * 2304) + sa_prow * 36 + sa_off + j * 4) * 4), \
                       hin + sa_row * UU + (k0) + sa_off + j * 4); \
    } while (0)

    // prefetch step-0 pre values
    float4 pv[4];
    {
        int t0i = dir ? (T_LEN - 1) : 0;
#pragma unroll
        for (int r = 0; r < 4; r++)
            pv[r] = *(const float4*)(pre + ((size_t)t0i * BB + b0 + r) * G4 + n0 + tx * 4);
    }

    for (int s = 0; s < T_LEN; s++) {
        int t = dir ? (T_LEN - 1 - s) : s;
        const float* hin = (s & 1) ? hbuf1 : hbuf0;
        float* hout      = (s & 1) ? hbuf0 : hbuf1;

        LSA(0, 0);  cp_commit();
        LSA(1, 32); cp_commit();
        LSA(2, 64); cp_commit();

        ull acc[4][4];
#pragma unroll
        for (int r = 0; r < 4; r++)
#pragma unroll
            for (int j = 0; j < 4; j++) acc[r][j] = 0ULL;

        for (int i = 0; i < 16; i++) {
            if (i < 13)      cp_wait<2>();
            else if (i < 15) cp_wait<1>();
            else             cp_wait<0>();
            __syncthreads();
            const float* Ap = Asm + (i & 3) * 2304;
            const float* Bp = Wsm + i * 1024;
#pragma unroll
            for (int kk4 = 0; kk4 < 8; kk4++) {
                ulonglong2 a2[4];
#pragma unroll
                for (int r = 0; r < 4; r++)
                    a2[r] = *(const ulonglong2*)(Ap + (r * 16 + ty) * 36 + kk4 * 4);
#pragma unroll
                for (int h = 0; h < 2; h++) {
                    int kk2 = kk4 * 2 + h;
                    ulonglong2 w01 = *(const ulonglong2*)(Bp + kk2 * 64 + tx * 4);
                    ulonglong2 w23 = *(const ulonglong2*)(Bp + kk2 * 64 + 32 + tx * 4);
#pragma unroll
                    for (int r = 0; r < 4; r++) {
                        ull a = h ? a2[r].y : a2[r].x;
                        fma2(acc[r][0], a, w01.x);
                        fma2(acc[r][1], a, w01.y);
                        fma2(acc[r][2], a, w23.x);
                        fma2(acc[r][3], a, w23.y);
                    }
                }
            }
            if (i + 3 < 16) { LSA((i + 3) & 3, (i + 3) * 32); cp_commit(); }
        }

        // epilogue: gates + state update (c stays in registers)
#pragma unroll
        for (int r = 0; r < 4; r++) {
            int b = b0 + r;
            float2 e0 = unpack2(acc[r][0]);
            float2 e1 = unpack2(acc[r][1]);
            float2 e2 = unpack2(acc[r][2]);
            float2 e3 = unpack2(acc[r][3]);
            float gi = e0.x + e0.y + pv[r].x + bb4.x;
            float gf = e1.x + e1.y + pv[r].y + bb4.y;
            float go = e2.x + e2.y + pv[r].z + bb4.z;
            float gg = e3.x + e3.y + pv[r].w + bb4.w;
            float ig = 1.f / (1.f + expf(-gi));
            float fg = 1.f / (1.f + expf(-gf));
            float og = 1.f / (1.f + expf(-go));
            float gt = tanhf(gg);
            float c = fg * cv[r] + ig * gt;
            float h = og * tanhf(c);
            cv[r] = c;
            hout[b * UU + u] = h;
            outp[((size_t)t * BB + b) * ostride + u] = h;
            if (outT) outT[(size_t)u * MTOT + t * BB + b] = h;
        }

        if (s + 1 < T_LEN) {
            // prefetch next step's pre values BEFORE the barrier — their
            // latency hides under the barrier wait
            int tn = dir ? (T_LEN - 2 - s) : (s + 1);
#pragma unroll
            for (int r = 0; r < 4; r++)
                pv[r] = *(const float4*)(pre + ((size_t)tn * BB + b0 + r) * G4 + n0 + tx * 4);
            gbar(ctr, (unsigned)(64 * (s + 1)));
        }
    }
#undef LSA
}

// ---------------- span feature gather ----------------------------------------
__global__ void build_hi(const int* __restrict__ sl, const int* __restrict__ sr,
                         const int* __restrict__ ll, const int* __restrict__ lr) {
    int idx = blockIdx.x * blockDim.x + threadIdx.x;
    const int NS = BB * 4 * 2048;
    int b, s, c, le, ri;
    float* dst;
    if (idx < NS) {
        b = idx / (4 * 2048); int r = idx - b * (4 * 2048);
        s = r / 2048; c = r - s * 2048;
        le = sl[b * 4 + s]; ri = sr[b * 4 + s];
        dst = g_hi_s + (size_t)b * 8192 + s * 2048 + c;
    } else {
        int j = idx - NS;
        b = j / (3 * 2048); int r = j - b * (3 * 2048);
        s = r / 2048; c = r - s * 2048;
        le = ll[b * 3 + s]; ri = lr[b * 3 + s];
        dst = g_hi_l + (size_t)b * 6144 + s * 2048 + c;
    }
    float v;
    if (c < 512) {
        v = g_in2[((size_t)ri * BB + b) * 1024 + c] - g_in2[((size_t)(le - 1) * BB + b) * 1024 + c];
    } else if (c < 1024) {
        int u = c - 512;
        v = g_fwd2[((size_t)ri * BB + b) * UU + u] - g_fwd2[((size_t)(le - 1) * BB + b) * UU + u];
    } else if (c < 1536) {
        int u = c - 1024;
        v = g_in2[((size_t)le * BB + b) * 1024 + 512 + u] - g_in2[((size_t)(ri + 1) * BB + b) * 1024 + 512 + u];
    } else {
        int u = c - 1536;
        v = g_back2[((size_t)le * BB + b) * UU + u] - g_back2[((size_t)(ri + 1) * BB + b) * UU + u];
    }
    *dst = v;
}

// ---------------- span hidden GEMM: M=64, split-K -----------------------------
__global__ void __launch_bounds__(256) span_gemm(
    const float* __restrict__ A, int lda, const float* __restrict__ B,
    float* __restrict__ Cpart) {
    __shared__ float AsT[16][68];
    __shared__ float Bs[16][68];
    int n0 = blockIdx.x * 64;
    int kbase = blockIdx.y * 512;
    int tid = threadIdx.x;
    int tx = tid & 15, ty = tid >> 4;
    float acc[4][4] = {{0}};
    int ab = tid >> 2, aseg = (tid & 3) * 4;
    int bkk = tid >> 4, bnn = (tid & 15) * 4;
    for (int k0 = kbase; k0 < kbase + 512; k0 += 16) {
        float4 av = *(const float4*)(A + (size_t)ab * lda + k0 + aseg);
        float4 wv = *(const float4*)(B + (size_t)(k0 + bkk) * HD + n0 + bnn);
        __syncthreads();
        AsT[aseg + 0][ab] = av.x; AsT[aseg + 1][ab] = av.y;
        AsT[aseg + 2][ab] = av.z; AsT[aseg + 3][ab] = av.w;
        *(float4*)&Bs[bkk][bnn] = wv;
        __syncthreads();
#pragma unroll
        for (int kk = 0; kk < 16; kk++) {
            float4 a = *(float4*)&AsT[kk][ty * 4];
            float4 w = *(float4*)&Bs[kk][tx * 4];
            float aa[4] = {a.x, a.y, a.z, a.w};
            float ww[4] = {w.x, w.y, w.z, w.w};
#pragma unroll
            for (int i = 0; i < 4; i++)
#pragma unroll
                for (int j = 0; j < 4; j++) acc[i][j] += aa[i] * ww[j];
        }
    }
#pragma unroll
    for (int i = 0; i < 4; i++) {
        int b = ty * 4 + i;
        float4 v = {acc[i][0], acc[i][1], acc[i][2], acc[i][3]};
        *(float4*)(Cpart + ((size_t)blockIdx.y * BB + b) * HD + n0 + tx * 4) = v;
    }
}

__global__ void reduce_relu(const float* __restrict__ part, int nch,
                            const float* __restrict__ bias, float* __restrict__ outh) {
    int idx = blockIdx.x * blockDim.x + threadIdx.x;
    int n = idx & (HD - 1);
    float s = bias[n];
    for (int ch = 0; ch < nch; ch++) s += part[(size_t)ch * BB * HD + idx];
    outh[idx] = fmaxf(s, 0.f);
}

// ---------------- output heads ------------------------------------------------
__global__ void out_heads(const float* __restrict__ soW, const float* __restrict__ sob,
                          const float* __restrict__ loW, const float* __restrict__ lob,
                          float* __restrict__ out) {
    __shared__ float s1[HD], s2[HD];
    int b = blockIdx.x, tid = threadIdx.x;
    for (int i = tid; i < HD; i += blockDim.x) {
        s1[i] = g_hs[b * HD + i];
        s2[i] = g_hl[b * HD + i];
    }
    __syncthreads();
    if (tid < 2) {
        float s = sob[tid];
        for (int k = 0; k < HD; k++) s += s1[k] * soW[k * 2 + tid];
        out[b * 2 + tid] = s;
    } else if (tid < 34) {
        int j = tid - 2;
        float s = lob[j];
        for (int k = 0; k < HD; k++) s += s2[k] * loW[k * 32 + j];
        out[128 + b * 32 + j] = s;
    }
}

// ---------------- host driver --------------------------------------------------
static float* sym(const void* symbol) {
    void* p = nullptr;
    cudaGetSymbolAddress(&p, symbol);
    return (float*)p;
}

extern "C" void kernel_launch(void* const* d_in, const int* in_sizes, int n_in,
                              void* d_out, int out_size) {
    const float* word_emb = (const float*)d_in[0];
    const float* tag_emb  = (const float*)d_in[1];
    const float* l1f_W = (const float*)d_in[2];
    const float* l1f_b = (const float*)d_in[3];
    const float* l1f_c0 = (const float*)d_in[4];
    const float* l1b_W = (const float*)d_in[5];
    const float* l1b_b = (const float*)d_in[6];
    const float* l1b_c0 = (const float*)d_in[7];
    const float* l2f_W = (const float*)d_in[8];
    const float* l2f_b = (const float*)d_in[9];
    const float* l2f_c0 = (const float*)d_in[10];
    const float* l2b_W = (const float*)d_in[11];
    const float* l2b_b = (const float*)d_in[12];
    const float* l2b_c0 = (const float*)d_in[13];
    const float* sh_W = (const float*)d_in[14];
    const float* sh_b = (const float*)d_in[15];
    const float* so_W = (const float*)d_in[16];
    const float* so_b = (const float*)d_in[17];
    const float* lh_W = (const float*)d_in[18];
    const float* lh_b = (const float*)d_in[19];
    const float* lo_W = (const float*)d_in[20];
    const float* lo_b = (const float*)d_in[21];
    const int* word_inds = (const int*)d_in[22];
    const int* tag_inds  = (const int*)d_in[23];
    const int* s_lefts  = (const int*)d_in[24];
    const int* s_rights = (const int*)d_in[25];
    const int* l_lefts  = (const int*)d_in[26];
    const int* l_rights = (const int*)d_in[27];
    float* out = (float*)d_out;

    float* p_sent  = sym(g_sent);
    float* p_sentT = sym(g_sentT);
    float* p_preF  = sym(g_preF);
    float* p_preB  = sym(g_preB);
    float* p_in2   = sym(g_in2);
    float* p_in2T  = sym(g_in2T);
    float* p_fwd2  = sym(g_fwd2);
    float* p_back2 = sym(g_back2);
    float* p_Wx1f = sym(g_Wx1f); float* p_Wx1b = sym(g_Wx1b);
    float* p_Wh1f = sym(g_Wh1f); float* p_Wh1b = sym(g_Wh1b);
    float* p_Wx2f = sym(g_Wx2f); float* p_Wx2b = sym(g_Wx2b);
    float* p_Wh2f = sym(g_Wh2f); float* p_Wh2b = sym(g_Wh2b);
    float* p_bv1f = sym(g_bv1f); float* p_bv1b = sym(g_bv1b);
    float* p_bv2f = sym(g_bv2f); float* p_bv2b = sym(g_bv2b);
    float* p_hi_s = sym(g_hi_s); float* p_hi_l = sym(g_hi_l);
    float* p_part_s = sym(g_part_s); float* p_part_l = sym(g_part_l);
    float* p_hs = sym(g_hs); float* p_hl = sym(g_hl);

    const int LSTM_SMEM = (16384 + 4 * 2304) * 4;   // 102,400 B
    static int smem_set = 0;
    if (!smem_set) {
        cudaFuncSetAttribute(lstm_layer, cudaFuncAttributeMaxDynamicSharedMemorySize,
                             LSTM_SMEM);
        smem_set = 1;
    }

    // 1) pack weights
    pack_lstm<<<2048, 256>>>(l1f_W, l1f_b, p_Wx1f, p_Wh1f, p_bv1f, SENT_D);
    pack_lstm<<<2048, 256>>>(l1b_W, l1b_b, p_Wx1b, p_Wh1b, p_bv1b, SENT_D);
    pack_lstm<<<4096, 256>>>(l2f_W, l2f_b, p_Wx2f, p_Wh2f, p_bv2f, 1024);
    pack_lstm<<<4096, 256>>>(l2b_W, l2b_b, p_Wx2b, p_Wh2b, p_bv2b, 1024);

    // 2) embeddings + transpose for GEMM A operand
    embed_kernel<<<(MTOT * SENT_D) / 256, 256>>>(word_emb, tag_emb, word_inds, tag_inds);
    transpose32<<<dim3(SENT_D / 32, MTOT / 32), dim3(32, 8)>>>(p_sent, p_sentT, MTOT, SENT_D);

    // 3) layer-1 input projections (16384 x 320 x 2048)
    dim3 gpre(G4 / 128, MTOT / 128);
    sgemm_nt<<<gpre, 256>>>(p_sentT, p_Wx1f, p_preF, SENT_D, MTOT, G4, G4);
    sgemm_nt<<<gpre, 256>>>(p_sentT, p_Wx1b, p_preB, SENT_D, MTOT, G4, G4);

    // 4) layer-1 recurrence: ONE fused persistent launch
    init_states<<<(BB * UU) / 256, 256>>>(l1f_c0, l1b_c0);
    lstm_layer<<<NCTA, 128, LSTM_SMEM>>>(
        p_preF, p_preB, p_Wh1f, p_Wh1b, p_bv1f, p_bv1b, l1f_c0, l1b_c0,
        p_in2, p_in2 + 512, p_in2T, p_in2T + (size_t)512 * MTOT, 1024);

    // 5) layer-2 input projections (16384 x 1024 x 2048)
    sgemm_nt<<<gpre, 256>>>(p_in2T, p_Wx2f, p_preF, 1024, MTOT, G4, G4);
    sgemm_nt<<<gpre, 256>>>(p_in2T, p_Wx2b, p_preB, 1024, MTOT, G4, G4);

    // 6) layer-2 recurrence
    init_states<<<(BB * UU) / 256, 256>>>(l2f_c0, l2b_c0);
    lstm_layer<<<NCTA, 128, LSTM_SMEM>>>(
        p_preF, p_preB, p_Wh2f, p_Wh2b, p_bv2f, p_bv2b, l2f_c0, l2b_c0,
        p_fwd2, p_back2, (float*)nullptr, (float*)nullptr, UU);

    // 7) span features
    build_hi<<<(BB * 7 * 2048) / 256, 256>>>(s_lefts, s_rights, l_lefts, l_rights);

    // 8) span hidden layers
    span_gemm<<<dim3(HD / 64, 16), 256>>>(p_hi_s, 8192, sh_W, p_part_s);
    span_gemm<<<dim3(HD / 64, 12), 256>>>(p_hi_l, 6144, lh_W, p_part_l);
    reduce_relu<<<(BB * HD) / 256, 256>>>(p_part_s, 16, sh_b, p_hs);
    reduce_relu<<<(BB * HD) / 256, 256>>>(p_part_l, 12, lh_b, p_hl);

    // 9) output heads
    out_heads<<<BB, 128>>>(so_W, so_b, lo_W, lo_b, out);
}

// round 15
// speedup vs baseline: 1.2624x; 1.0106x over previous
#include <cuda_runtime.h>
#include <math.h>
#include <stdint.h>

#define T_LEN 256
#define BB 64
#define SENT_D 320
#define UU 512
#define G4 2048
#define HD 1024
#define MTOT (T_LEN * BB)          // 16384
#define NCTA 128

typedef unsigned long long ull;

// ---------------- packed f32x2 + cp.async helpers ----------------------------
__device__ __forceinline__ void fma2(ull& d, ull a, ull b) {
    asm("fma.rn.f32x2 %0, %1, %2, %0;" : "+l"(d) : "l"(a), "l"(b));
}
__device__ __forceinline__ ull dup2(float x) {
    ull r;
    asm("mov.b64 %0, {%1, %1};" : "=l"(r) : "f"(x));
    return r;
}
__device__ __forceinline__ float2 unpack2(ull v) {
    float2 r;
    asm("mov.b64 {%0, %1}, %2;" : "=f"(r.x), "=f"(r.y) : "l"(v));
    return r;
}
__device__ __forceinline__ void cp_async16(uint32_t saddr, const void* gptr) {
    asm volatile("cp.async.cg.shared.global [%0], [%1], 16;" :: "r"(saddr), "l"(gptr));
}
__device__ __forceinline__ void cp_commit() {
    asm volatile("cp.async.commit_group;" ::: "memory");
}
template<int N> __device__ __forceinline__ void cp_wait() {
    asm volatile("cp.async.wait_group %0;" :: "n"(N) : "memory");
}

// ---------------- scratch (device globals; no allocs allowed) ----------------
__device__ float g_sent[MTOT * SENT_D];
__device__ float g_sentT[SENT_D * MTOT];
__device__ float g_preF[(size_t)MTOT * G4];
__device__ float g_preB[(size_t)MTOT * G4];
__device__ float g_in2[(size_t)MTOT * 1024];
__device__ float g_in2T[(size_t)1024 * MTOT];
__device__ float g_fwd2[(size_t)MTOT * UU];
__device__ float g_back2[(size_t)MTOT * UU];

__device__ float g_Wx1f[SENT_D * G4], g_Wx1b[SENT_D * G4];
__device__ float g_Wh1f[UU * G4],     g_Wh1b[UU * G4];   // k-paired + plane layout
__device__ float g_Wx2f[1024 * G4],   g_Wx2b[1024 * G4];
__device__ float g_Wh2f[UU * G4],     g_Wh2b[UU * G4];
__device__ float g_bv1f[G4], g_bv1b[G4], g_bv2f[G4], g_bv2b[G4];

__device__ float g_hFa[BB * UU], g_hFb[BB * UU];
__device__ float g_hBa[BB * UU], g_hBb[BB * UU];

__device__ float g_hi_s[BB * 8192];
__device__ float g_hi_l[BB * 6144];
__device__ float g_part_s[16 * BB * HD];
__device__ float g_part_l[12 * BB * HD];
__device__ float g_hs[BB * HD], g_hl[BB * HD];

__device__ unsigned g_sc;   // monotonic grid-barrier counter (R12 proven)

// Grid barrier (R12, proven): every thread drains its own STG writes to the
// gpu coherence point BEFORE arriving, then t0 does release-add+acquire-poll.
__device__ __forceinline__ void gbar(unsigned target) {
    __syncthreads();
    asm volatile("fence.acq_rel.gpu;" ::: "memory");
    if (threadIdx.x == 0) {
        asm volatile("red.release.gpu.add.u32 [%0], 1;" :: "l"(&g_sc) : "memory");
        unsigned x;
        do {
            asm volatile("ld.acquire.gpu.u32 %0, [%1];" : "=r"(x) : "l"(&g_sc) : "memory");
        } while (x < target);
    }
    __syncthreads();
}

// ---------------- weight packing ----------------------------------------------
// Wx: column n = u*4 + k. Wh: k-paired + per-32-gate-tile plane layout.
__global__ void pack_lstm(const float* __restrict__ W, const float* __restrict__ b,
                          float* __restrict__ Wx, float* __restrict__ Wh,
                          float* __restrict__ bv, int din) {
    int total = 4 * (din + UU) * UU;
    int stride = gridDim.x * blockDim.x;
    for (int idx = blockIdx.x * blockDim.x + threadIdx.x; idx < total; idx += stride) {
        int k = idx / ((din + UU) * UU);
        int rem = idx - k * ((din + UU) * UU);
        int d = rem / UU;
        int u = rem - d * UU;
        float v = W[idx];
        int n = u * 4 + k;
        if (d < din) {
            Wx[(size_t)d * G4 + n] = v;
        } else {
            int kd = d - din;
            int tile = n >> 5, loc = n & 31;
            int txx = loc >> 2, j = loc & 3;
            int col = tile * 64 + (j >> 1) * 32 + txx * 4 + ((j & 1) << 1) + (kd & 1);
            Wh[(size_t)(kd >> 1) * 4096 + col] = v;
        }
    }
    for (int i = blockIdx.x * blockDim.x + threadIdx.x; i < G4; i += stride) {
        int k = i & 3, u = i >> 2;
        bv[i] = b[k * UU + u];
    }
}

// ---------------- embedding gather + concat ----------------------------------
__global__ void embed_kernel(const float* __restrict__ we, const float* __restrict__ te,
                             const int* __restrict__ wi, const int* __restrict__ ti) {
    int idx = blockIdx.x * blockDim.x + threadIdx.x;
    int tb = idx / SENT_D;
    int j = idx - tb * SENT_D;
    float v;
    if (j < 256) v = we[(size_t)wi[tb] * 256 + j];
    else         v = te[(size_t)ti[tb] * 64 + (j - 256)];
    g_sent[idx] = v;
}

// ---------------- tiled transpose --------------------------------------------
__global__ void transpose32(const float* __restrict__ src, float* __restrict__ dst,
                            int R, int Cc) {
    __shared__ float tl[32][33];
    int c0 = blockIdx.x * 32, r0 = blockIdx.y * 32;
    int tx = threadIdx.x, ty = threadIdx.y;   // 32 x 8
#pragma unroll
    for (int i = 0; i < 32; i += 8)
        tl[ty + i][tx] = src[(size_t)(r0 + ty + i) * Cc + c0 + tx];
    __syncthreads();
#pragma unroll
    for (int i = 0; i < 32; i += 8)
        dst[(size_t)(c0 + ty + i) * R + r0 + tx] = tl[tx][ty + i];
}

// ---------------- LSTM h-state init + barrier counter reset -------------------
__global__ void init_states(const float* __restrict__ c0f, const float* __restrict__ c0b) {
    int idx = blockIdx.x * blockDim.x + threadIdx.x;   // B*U = 32768
    if (idx == 0) g_sc = 0;
    int u = idx & (UU - 1);
    g_hFa[idx] = tanhf(c0f[u]);
    g_hBa[idx] = tanhf(c0b[u]);
}

// ---------------- big GEMM: C = AT^T @ B, cp.async 4-stage ring ---------------
// One __syncthreads per k-tile; 3 tiles in flight hide L2/DRAM latency.
__global__ void __launch_bounds__(256) sgemm_nt(
    const float* __restrict__ AT, const float* __restrict__ B, float* __restrict__ C,
    int K, int ldat, int ldb, int ldc) {
    extern __shared__ float smg[];
    float* Asm = smg;                 // 4 stages x 2112 floats
    float* Bsm = smg + 4 * 2112;      // 4 stages x 2112 floats
    int m0 = blockIdx.y * 128, n0 = blockIdx.x * 128;
    int tid = threadIdx.x;
    int tx = tid & 15, ty = tid >> 4;
    uint32_t as0 = (uint32_t)__cvta_generic_to_shared(Asm);
    uint32_t bs0 = (uint32_t)__cvta_generic_to_shared(Bsm);
    int akk = tid >> 5, aoff = (tid & 31) * 4;
    int niter = K >> 4;

    ull acc[4][8];
#pragma unroll
    for (int p = 0; p < 4; p++)
#pragma unroll
        for (int j = 0; j < 8; j++) acc[p][j] = 0ULL;

#define SG_STAGE(st, kk0) do { \
        cp_async16(as0 + (uint32_t)(((st) * 2112 + akk * 132 + aoff) * 4), \
                   AT + (size_t)((kk0) + akk) * ldat + m0 + aoff); \
        cp_async16(as0 + (uint32_t)(((st) * 2112 + (akk + 8) * 132 + aoff) * 4), \
                   AT + (size_t)((kk0) + akk + 8) * ldat + m0 + aoff); \
        cp_async16(bs0 + (uint32_t)(((st) * 2112 + akk * 132 + aoff) * 4), \
                   B + (size_t)((kk0) + akk) * ldb + n0 + aoff); \
        cp_async16(bs0 + (uint32_t)(((st) * 2112 + (akk + 8) * 132 + aoff) * 4), \
                   B + (size_t)((kk0) + akk + 8) * ldb + n0 + aoff); \
    } while (0)

    SG_STAGE(0, 0);  cp_commit();
    SG_STAGE(1, 16); cp_commit();
    SG_STAGE(2, 32); cp_commit();

    for (int i = 0; i < niter; i++) {
        int rem = niter - i;
        if (rem >= 3)      cp_wait<2>();
        else if (rem == 2) cp_wait<1>();
        else               cp_wait<0>();
        __syncthreads();
        const float* Ap = Asm + (i & 3) * 2112;
        const float* Bp = Bsm + (i & 3) * 2112;
#pragma unroll
        for (int kk = 0; kk < 16; kk++) {
            ull ap[4];
#pragma unroll
            for (int q = 0; q < 4; q++)
                ap[q] = *(const ull*)(Ap + kk * 132 + ty * 8 + 2 * q);
            float4 bv0 = *(const float4*)(Bp + kk * 132 + tx * 8);
            float4 bv1 = *(const float4*)(Bp + kk * 132 + tx * 8 + 4);
            ull bd[8] = {dup2(bv0.x), dup2(bv0.y), dup2(bv0.z), dup2(bv0.w),
                         dup2(bv1.x), dup2(bv1.y), dup2(bv1.z), dup2(bv1.w)};
#pragma unroll
            for (int q = 0; q < 4; q++)
#pragma unroll
                for (int j = 0; j < 8; j++) fma2(acc[q][j], ap[q], bd[j]);
        }
        if (i + 3 < niter) { SG_STAGE((i + 3) & 3, (i + 3) * 16); cp_commit(); }
    }
#undef SG_STAGE

#pragma unroll
    for (int q = 0; q < 4; q++) {
        float v0[8], v1[8];
#pragma unroll
        for (int j = 0; j < 8; j++) {
            float2 t = unpack2(acc[q][j]);
            v0[j] = t.x; v1[j] = t.y;
        }
        float* c0 = C + (size_t)(m0 + ty * 8 + 2 * q) * ldc + n0 + tx * 8;
        float* c1 = c0 + ldc;
        *(float4*)c0 = make_float4(v0[0], v0[1], v0[2], v0[3]);
        *(float4*)(c0 + 4) = make_float4(v0[4], v0[5], v0[6], v0[7]);
        *(float4*)c1 = make_float4(v1[0], v1[1], v1[2], v1[3]);
        *(float4*)(c1 + 4) = make_float4(v1[4], v1[5], v1[6], v1[7]);
    }
}

// ---------------- fused recurrence layer (R12, proven) ------------------------
__global__ void __launch_bounds__(128) lstm_layer(
    const float* __restrict__ preF, const float* __restrict__ preB,
    const float* __restrict__ WpF,  const float* __restrict__ WpB,
    const float* __restrict__ bvF,  const float* __restrict__ bvB,
    const float* __restrict__ c0F,  const float* __restrict__ c0B,
    float* __restrict__ outF, float* __restrict__ outB,
    float* __restrict__ outTF, float* __restrict__ outTB, int ostride) {
    extern __shared__ float sm[];
    float* Wsm = sm;                    // 16384 floats (resident W slice)
    float* Asm = sm + 16384;            // 4 stages x 2304 floats

    int blk = blockIdx.x;
    int dir = blk >> 6;
    int nb  = blk & 63;
    int n0  = nb * 32;

    const float* pre = dir ? preB : preF;
    const float* Wp  = dir ? WpB : WpF;
    const float* bv  = dir ? bvB : bvF;
    const float* c0p = dir ? c0B : c0F;
    float* outp  = dir ? outB : outF;
    float* outT  = dir ? outTB : outTF;
    float* hbuf0 = dir ? g_hBa : g_hFa;
    float* hbuf1 = dir ? g_hBb : g_hFb;

    int tid = threadIdx.x;
    int tx = tid >> 4;            // 0..7 : unit within tile
    int ty = tid & 15;            // 0..15: b-group of 4
    int b0 = ty * 4;
    int u = nb * 8 + tx;

    uint32_t wsb = (uint32_t)__cvta_generic_to_shared(Wsm);
    uint32_t asb = (uint32_t)__cvta_generic_to_shared(Asm);

    // load resident W slice: each thread fills its contiguous 128-float span
#pragma unroll
    for (int j = 0; j < 32; j++) {
        int f = tid * 128 + j * 4;
        int row = f >> 6, col = f & 63;
        cp_async16(wsb + (uint32_t)f * 4, Wp + (size_t)row * 4096 + nb * 64 + col);
    }
    cp_commit();

    float4 bb4 = *(const float4*)(bv + n0 + tx * 4);
    float c0v = c0p[u];
    float cv[4] = {c0v, c0v, c0v, c0v};

    // A staging assignment: permuted rows, stride 36
    int sa_row = tid >> 1, sa_off = (tid & 1) * 16;
    int sa_prow = (sa_row & 3) * 16 + (sa_row >> 2);

    cp_wait<0>();
    __syncthreads();   // W resident ready

#define LSA(st, k0) do { \
        _Pragma("unroll") \
        for (int j = 0; j < 4; j++) \
            cp_async16(asb + (uint32_t)((((st) * 2304) + sa_prow * 36 + sa_off + j * 4) * 4), \
                       hin + sa_row * UU + (k0) + sa_off + j * 4); \
    } while (0)

    for (int s = 0; s < T_LEN; s++) {
        int t = dir ? (T_LEN - 1 - s) : s;
        const float* hin = (s & 1) ? hbuf1 : hbuf0;
        float* hout      = (s & 1) ? hbuf0 : hbuf1;

        // per-step pre loads (latency hides under staging + k-loop)
        float4 pv[4];
#pragma unroll
        for (int r = 0; r < 4; r++)
            pv[r] = *(const float4*)(pre + ((size_t)t * BB + b0 + r) * G4 + n0 + tx * 4);

        LSA(0, 0);  cp_commit();
        LSA(1, 32); cp_commit();
        LSA(2, 64); cp_commit();

        ull acc[4][4];
#pragma unroll
        for (int r = 0; r < 4; r++)
#pragma unroll
            for (int j = 0; j < 4; j++) acc[r][j] = 0ULL;

        for (int i = 0; i < 16; i++) {
            if (i < 13)      cp_wait<2>();
            else if (i < 15) cp_wait<1>();
            else             cp_wait<0>();
            __syncthreads();
            const float* Ap = Asm + (i & 3) * 2304;
            const float* Bp = Wsm + i * 1024;
#pragma unroll
            for (int kk4 = 0; kk4 < 8; kk4++) {
                ulonglong2 a2[4];
#pragma unroll
                for (int r = 0; r < 4; r++)
                    a2[r] = *(const ulonglong2*)(Ap + (r * 16 + ty) * 36 + kk4 * 4);
#pragma unroll
                for (int h = 0; h < 2; h++) {
                    int kk2 = kk4 * 2 + h;
                    ulonglong2 w01 = *(const ulonglong2*)(Bp + kk2 * 64 + tx * 4);
                    ulonglong2 w23 = *(const ulonglong2*)(Bp + kk2 * 64 + 32 + tx * 4);
#pragma unroll
                    for (int r = 0; r < 4; r++) {
                        ull a = h ? a2[r].y : a2[r].x;
                        fma2(acc[r][0], a, w01.x);
                        fma2(acc[r][1], a, w01.y);
                        fma2(acc[r][2], a, w23.x);
                        fma2(acc[r][3], a, w23.y);
                    }
                }
            }
            if (i + 3 < 16) { LSA((i + 3) & 3, (i + 3) * 32); cp_commit(); }
        }

        // epilogue: gates + state update (c stays in registers)
#pragma unroll
        for (int r = 0; r < 4; r++) {
            int b = b0 + r;
            float2 e0 = unpack2(acc[r][0]);
            float2 e1 = unpack2(acc[r][1]);
            float2 e2 = unpack2(acc[r][2]);
            float2 e3 = unpack2(acc[r][3]);
            float gi = e0.x + e0.y + pv[r].x + bb4.x;
            float gf = e1.x + e1.y + pv[r].y + bb4.y;
            float go = e2.x + e2.y + pv[r].z + bb4.z;
            float gg = e3.x + e3.y + pv[r].w + bb4.w;
            float ig = 1.f / (1.f + expf(-gi));
            float fg = 1.f / (1.f + expf(-gf));
            float og = 1.f / (1.f + expf(-go));
            float gt = tanhf(gg);
            float c = fg * cv[r] + ig * gt;
            float h = og * tanhf(c);
            cv[r] = c;
            hout[b * UU + u] = h;
            outp[((size_t)t * BB + b) * ostride + u] = h;
            if (outT) outT[(size_t)u * MTOT + t * BB + b] = h;
        }

        if (s + 1 < T_LEN) gbar((unsigned)(NCTA * (s + 1)));
    }
#undef LSA
}

// ---------------- span feature gather ----------------------------------------
__global__ void build_hi(const int* __restrict__ sl, const int* __restrict__ sr,
                         const int* __restrict__ ll, const int* __restrict__ lr) {
    int idx = blockIdx.x * blockDim.x + threadIdx.x;
    const int NS = BB * 4 * 2048;
    int b, s, c, le, ri;
    float* dst;
    if (idx < NS) {
        b = idx / (4 * 2048); int r = idx - b * (4 * 2048);
        s = r / 2048; c = r - s * 2048;
        le = sl[b * 4 + s]; ri = sr[b * 4 + s];
        dst = g_hi_s + (size_t)b * 8192 + s * 2048 + c;
    } else {
        int j = idx - NS;
        b = j / (3 * 2048); int r = j - b * (3 * 2048);
        s = r / 2048; c = r - s * 2048;
        le = ll[b * 3 + s]; ri = lr[b * 3 + s];
        dst = g_hi_l + (size_t)b * 6144 + s * 2048 + c;
    }
    float v;
    if (c < 512) {
        v = g_in2[((size_t)ri * BB + b) * 1024 + c] - g_in2[((size_t)(le - 1) * BB + b) * 1024 + c];
    } else if (c < 1024) {
        int u = c - 512;
        v = g_fwd2[((size_t)ri * BB + b) * UU + u] - g_fwd2[((size_t)(le - 1) * BB + b) * UU + u];
    } else if (c < 1536) {
        int u = c - 1024;
        v = g_in2[((size_t)le * BB + b) * 1024 + 512 + u] - g_in2[((size_t)(ri + 1) * BB + b) * 1024 + 512 + u];
    } else {
        int u = c - 1536;
        v = g_back2[((size_t)le * BB + b) * UU + u] - g_back2[((size_t)(ri + 1) * BB + b) * UU + u];
    }
    *dst = v;
}

// ---------------- span hidden GEMM: M=64, split-K -----------------------------
__global__ void __launch_bounds__(256) span_gemm(
    const float* __restrict__ A, int lda, const float* __restrict__ B,
    float* __restrict__ Cpart) {
    __shared__ float AsT[16][68];
    __shared__ float Bs[16][68];
    int n0 = blockIdx.x * 64;
    int kbase = blockIdx.y * 512;
    int tid = threadIdx.x;
    int tx = tid & 15, ty = tid >> 4;
    float acc[4][4] = {{0}};
    int ab = tid >> 2, aseg = (tid & 3) * 4;
    int bkk = tid >> 4, bnn = (tid & 15) * 4;
    for (int k0 = kbase; k0 < kbase + 512; k0 += 16) {
        float4 av = *(const float4*)(A + (size_t)ab * lda + k0 + aseg);
        float4 wv = *(const float4*)(B + (size_t)(k0 + bkk) * HD + n0 + bnn);
        __syncthreads();
        AsT[aseg + 0][ab] = av.x; AsT[aseg + 1][ab] = av.y;
        AsT[aseg + 2][ab] = av.z; AsT[aseg + 3][ab] = av.w;
        *(float4*)&Bs[bkk][bnn] = wv;
        __syncthreads();
#pragma unroll
        for (int kk = 0; kk < 16; kk++) {
            float4 a = *(float4*)&AsT[kk][ty * 4];
            float4 w = *(float4*)&Bs[kk][tx * 4];
            float aa[4] = {a.x, a.y, a.z, a.w};
            float ww[4] = {w.x, w.y, w.z, w.w};
#pragma unroll
            for (int i = 0; i < 4; i++)
#pragma unroll
                for (int j = 0; j < 4; j++) acc[i][j] += aa[i] * ww[j];
        }
    }
#pragma unroll
    for (int i = 0; i < 4; i++) {
        int b = ty * 4 + i;
        float4 v = {acc[i][0], acc[i][1], acc[i][2], acc[i][3]};
        *(float4*)(Cpart + ((size_t)blockIdx.y * BB + b) * HD + n0 + tx * 4) = v;
    }
}

__global__ void reduce_relu(const float* __restrict__ part, int nch,
                            const float* __restrict__ bias, float* __restrict__ outh) {
    int idx = blockIdx.x * blockDim.x + threadIdx.x;
    int n = idx & (HD - 1);
    float s = bias[n];
    for (int ch = 0; ch < nch; ch++) s += part[(size_t)ch * BB * HD + idx];
    outh[idx] = fmaxf(s, 0.f);
}

// ---------------- output heads ------------------------------------------------
__global__ void out_heads(const float* __restrict__ soW, const float* __restrict__ sob,
                          const float* __restrict__ loW, const float* __restrict__ lob,
                          float* __restrict__ out) {
    __shared__ float s1[HD], s2[HD];
    int b = blockIdx.x, tid = threadIdx.x;
    for (int i = tid; i < HD; i += blockDim.x) {
        s1[i] = g_hs[b * HD + i];
        s2[i] = g_hl[b * HD + i];
    }
    __syncthreads();
    if (tid < 2) {
        float s = sob[tid];
        for (int k = 0; k < HD; k++) s += s1[k] * soW[k * 2 + tid];
        out[b * 2 + tid] = s;
    } else if (tid < 34) {
        int j = tid - 2;
        float s = lob[j];
        for (int k = 0; k < HD; k++) s += s2[k] * loW[k * 32 + j];
        out[128 + b * 32 + j] = s;
    }
}

// ---------------- host driver --------------------------------------------------
static float* sym(const void* symbol) {
    void* p = nullptr;
    cudaGetSymbolAddress(&p, symbol);
    return (float*)p;
}

extern "C" void kernel_launch(void* const* d_in, const int* in_sizes, int n_in,
                              void* d_out, int out_size) {
    const float* word_emb = (const float*)d_in[0];
    const float* tag_emb  = (const float*)d_in[1];
    const float* l1f_W = (const float*)d_in[2];
    const float* l1f_b = (const float*)d_in[3];
    const float* l1f_c0 = (const float*)d_in[4];
    const float* l1b_W = (const float*)d_in[5];
    const float* l1b_b = (const float*)d_in[6];
    const float* l1b_c0 = (const float*)d_in[7];
    const float* l2f_W = (const float*)d_in[8];
    const float* l2f_b = (const float*)d_in[9];
    const float* l2f_c0 = (const float*)d_in[10];
    const float* l2b_W = (const float*)d_in[11];
    const float* l2b_b = (const float*)d_in[12];
    const float* l2b_c0 = (const float*)d_in[13];
    const float* sh_W = (const float*)d_in[14];
    const float* sh_b = (const float*)d_in[15];
    const float* so_W = (const float*)d_in[16];
    const float* so_b = (const float*)d_in[17];
    const float* lh_W = (const float*)d_in[18];
    const float* lh_b = (const float*)d_in[19];
    const float* lo_W = (const float*)d_in[20];
    const float* lo_b = (const float*)d_in[21];
    const int* word_inds = (const int*)d_in[22];
    const int* tag_inds  = (const int*)d_in[23];
    const int* s_lefts  = (const int*)d_in[24];
    const int* s_rights = (const int*)d_in[25];
    const int* l_lefts  = (const int*)d_in[26];
    const int* l_rights = (const int*)d_in[27];
    float* out = (float*)d_out;

    float* p_sent  = sym(g_sent);
    float* p_sentT = sym(g_sentT);
    float* p_preF  = sym(g_preF);
    float* p_preB  = sym(g_preB);
    float* p_in2   = sym(g_in2);
    float* p_in2T  = sym(g_in2T);
    float* p_fwd2  = sym(g_fwd2);
    float* p_back2 = sym(g_back2);
    float* p_Wx1f = sym(g_Wx1f); float* p_Wx1b = sym(g_Wx1b);
    float* p_Wh1f = sym(g_Wh1f); float* p_Wh1b = sym(g_Wh1b);
    float* p_Wx2f = sym(g_Wx2f); float* p_Wx2b = sym(g_Wx2b);
    float* p_Wh2f = sym(g_Wh2f); float* p_Wh2b = sym(g_Wh2b);
    float* p_bv1f = sym(g_bv1f); float* p_bv1b = sym(g_bv1b);
    float* p_bv2f = sym(g_bv2f); float* p_bv2b = sym(g_bv2b);
    float* p_hi_s = sym(g_hi_s); float* p_hi_l = sym(g_hi_l);
    float* p_part_s = sym(g_part_s); float* p_part_l = sym(g_part_l);
    float* p_hs = sym(g_hs); float* p_hl = sym(g_hl);

    const int LSTM_SMEM = (16384 + 4 * 2304) * 4;   // 102,400 B
    const int SG_SMEM   = (8 * 2112) * 4;           // 67,584 B
    static int smem_set = 0;
    if (!smem_set) {
        cudaFuncSetAttribute(lstm_layer, cudaFuncAttributeMaxDynamicSharedMemorySize,
                             LSTM_SMEM);
        cudaFuncSetAttribute(sgemm_nt, cudaFuncAttributeMaxDynamicSharedMemorySize,
                             SG_SMEM);
        smem_set = 1;
    }

    // 1) pack weights
    pack_lstm<<<2048, 256>>>(l1f_W, l1f_b, p_Wx1f, p_Wh1f, p_bv1f, SENT_D);
    pack_lstm<<<2048, 256>>>(l1b_W, l1b_b, p_Wx1b, p_Wh1b, p_bv1b, SENT_D);
    pack_lstm<<<4096, 256>>>(l2f_W, l2f_b, p_Wx2f, p_Wh2f, p_bv2f, 1024);
    pack_lstm<<<4096, 256>>>(l2b_W, l2b_b, p_Wx2b, p_Wh2b, p_bv2b, 1024);

    // 2) embeddings + transpose for GEMM A operand
    embed_kernel<<<(MTOT * SENT_D) / 256, 256>>>(word_emb, tag_emb, word_inds, tag_inds);
    transpose32<<<dim3(SENT_D / 32, MTOT / 32), dim3(32, 8)>>>(p_sent, p_sentT, MTOT, SENT_D);

    // 3) layer-1 input projections (16384 x 320 x 2048)
    dim3 gpre(G4 / 128, MTOT / 128);
    sgemm_nt<<<gpre, 256, SG_SMEM>>>(p_sentT, p_Wx1f, p_preF, SENT_D, MTOT, G4, G4);
    sgemm_nt<<<gpre, 256, SG_SMEM>>>(p_sentT, p_Wx1b, p_preB, SENT_D, MTOT, G4, G4);

    // 4) layer-1 recurrence: ONE fused persistent launch
    init_states<<<(BB * UU) / 256, 256>>>(l1f_c0, l1b_c0);
    lstm_layer<<<NCTA, 128, LSTM_SMEM>>>(
        p_preF, p_preB, p_Wh1f, p_Wh1b, p_bv1f, p_bv1b, l1f_c0, l1b_c0,
        p_in2, p_in2 + 512, p_in2T, p_in2T + (size_t)512 * MTOT, 1024);

    // 5) layer-2 input projections (16384 x 1024 x 2048)
    sgemm_nt<<<gpre, 256, SG_SMEM>>>(p_in2T, p_Wx2f, p_preF, 1024, MTOT, G4, G4);
    sgemm_nt<<<gpre, 256, SG_SMEM>>>(p_in2T, p_Wx2b, p_preB, 1024, MTOT, G4, G4);

    // 6) layer-2 recurrence
    init_states<<<(BB * UU) / 256, 256>>>(l2f_c0, l2b_c0);
    lstm_layer<<<NCTA, 128, LSTM_SMEM>>>(
        p_preF, p_preB, p_Wh2f, p_Wh2b, p_bv2f, p_bv2b, l2f_c0, l2b_c0,
        p_fwd2, p_back2, (float*)nullptr, (float*)nullptr, UU);

    // 7) span features
    build_hi<<<(BB * 7 * 2048) / 256, 256>>>(s_lefts, s_rights, l_lefts, l_rights);

    // 8) span hidden layers
    span_gemm<<<dim3(HD / 64, 16), 256>>>(p_hi_s, 8192, sh_W, p_part_s);
    span_gemm<<<dim3(HD / 64, 12), 256>>>(p_hi_l, 6144, lh_W, p_part_l);
    reduce_relu<<<(BB * HD) / 256, 256>>>(p_part_s, 16, sh_b, p_hs);
    reduce_relu<<<(BB * HD) / 256, 256>>>(p_part_l, 12, lh_b, p_hl);

    // 9) output heads
    out_heads<<<BB, 128>>>(so_W, so_b, lo_W, lo_b, out);
}

// round 16
// speedup vs baseline: 1.2719x; 1.0075x over previous
#include <cuda_runtime.h>
#include <math.h>
#include <stdint.h>

#define T_LEN 256
#define BB 64
#define SENT_D 320
#define UU 512
#define G4 2048
#define HD 1024
#define MTOT (T_LEN * BB)          // 16384
#define NCTA 128

typedef unsigned long long ull;

// ---------------- packed f32x2 + cp.async helpers ----------------------------
__device__ __forceinline__ void fma2(ull& d, ull a, ull b) {
    asm("fma.rn.f32x2 %0, %1, %2, %0;" : "+l"(d) : "l"(a), "l"(b));
}
__device__ __forceinline__ ull dup2(float x) {
    ull r;
    asm("mov.b64 %0, {%1, %1};" : "=l"(r) : "f"(x));
    return r;
}
__device__ __forceinline__ float2 unpack2(ull v) {
    float2 r;
    asm("mov.b64 {%0, %1}, %2;" : "=f"(r.x), "=f"(r.y) : "l"(v));
    return r;
}
__device__ __forceinline__ void cp_async16(uint32_t saddr, const void* gptr) {
    asm volatile("cp.async.cg.shared.global [%0], [%1], 16;" :: "r"(saddr), "l"(gptr));
}
__device__ __forceinline__ void cp_commit() {
    asm volatile("cp.async.commit_group;" ::: "memory");
}
template<int N> __device__ __forceinline__ void cp_wait() {
    asm volatile("cp.async.wait_group %0;" :: "n"(N) : "memory");
}

// fast activations (MUFU EX2 + RCP; overflow-safe at +/-inf)
__device__ __forceinline__ float fsig(float x) {
    return __fdividef(1.f, 1.f + __expf(-x));
}
__device__ __forceinline__ float ftanh_f(float x) {
    return 1.f - 2.f * __fdividef(1.f, __expf(2.f * x) + 1.f);
}

// ---------------- scratch (device globals; no allocs allowed) ----------------
__device__ float g_sent[MTOT * SENT_D];
__device__ float g_sentT[SENT_D * MTOT];
__device__ float g_preF[(size_t)MTOT * G4];
__device__ float g_preB[(size_t)MTOT * G4];
__device__ float g_in2[(size_t)MTOT * 1024];
__device__ float g_in2T[(size_t)1024 * MTOT];
__device__ float g_fwd2[(size_t)MTOT * UU];
__device__ float g_back2[(size_t)MTOT * UU];

__device__ float g_Wx1f[SENT_D * G4], g_Wx1b[SENT_D * G4];
__device__ float g_Wh1f[UU * G4],     g_Wh1b[UU * G4];   // k-paired + plane layout
__device__ float g_Wx2f[1024 * G4],   g_Wx2b[1024 * G4];
__device__ float g_Wh2f[UU * G4],     g_Wh2b[UU * G4];
__device__ float g_bv1f[G4], g_bv1b[G4], g_bv2f[G4], g_bv2b[G4];

__device__ float g_hFa[BB * UU], g_hFb[BB * UU];
__device__ float g_hBa[BB * UU], g_hBb[BB * UU];

__device__ float g_hi_s[BB * 8192];
__device__ float g_hi_l[BB * 6144];
__device__ float g_part_s[16 * BB * HD];
__device__ float g_part_l[12 * BB * HD];
__device__ float g_hs[BB * HD], g_hl[BB * HD];

__device__ unsigned g_sc;   // monotonic grid-barrier counter (R12 proven)

// ---------------- weight packing ----------------------------------------------
// Wx: column n = u*4 + k. Wh: k-paired + per-32-gate-tile plane layout.
__global__ void pack_lstm(const float* __restrict__ W, const float* __restrict__ b,
                          float* __restrict__ Wx, float* __restrict__ Wh,
                          float* __restrict__ bv, int din) {
    int total = 4 * (din + UU) * UU;
    int stride = gridDim.x * blockDim.x;
    for (int idx = blockIdx.x * blockDim.x + threadIdx.x; idx < total; idx += stride) {
        int k = idx / ((din + UU) * UU);
        int rem = idx - k * ((din + UU) * UU);
        int d = rem / UU;
        int u = rem - d * UU;
        float v = W[idx];
        int n = u * 4 + k;
        if (d < din) {
            Wx[(size_t)d * G4 + n] = v;
        } else {
            int kd = d - din;
            int tile = n >> 5, loc = n & 31;
            int txx = loc >> 2, j = loc & 3;
            int col = tile * 64 + (j >> 1) * 32 + txx * 4 + ((j & 1) << 1) + (kd & 1);
            Wh[(size_t)(kd >> 1) * 4096 + col] = v;
        }
    }
    for (int i = blockIdx.x * blockDim.x + threadIdx.x; i < G4; i += stride) {
        int k = i & 3, u = i >> 2;
        bv[i] = b[k * UU + u];
    }
}

// ---------------- embedding gather + concat ----------------------------------
__global__ void embed_kernel(const float* __restrict__ we, const float* __restrict__ te,
                             const int* __restrict__ wi, const int* __restrict__ ti) {
    int idx = blockIdx.x * blockDim.x + threadIdx.x;
    int tb = idx / SENT_D;
    int j = idx - tb * SENT_D;
    float v;
    if (j < 256) v = we[(size_t)wi[tb] * 256 + j];
    else         v = te[(size_t)ti[tb] * 64 + (j - 256)];
    g_sent[idx] = v;
}

// ---------------- tiled transpose --------------------------------------------
__global__ void transpose32(const float* __restrict__ src, float* __restrict__ dst,
                            int R, int Cc) {
    __shared__ float tl[32][33];
    int c0 = blockIdx.x * 32, r0 = blockIdx.y * 32;
    int tx = threadIdx.x, ty = threadIdx.y;   // 32 x 8
#pragma unroll
    for (int i = 0; i < 32; i += 8)
        tl[ty + i][tx] = src[(size_t)(r0 + ty + i) * Cc + c0 + tx];
    __syncthreads();
#pragma unroll
    for (int i = 0; i < 32; i += 8)
        dst[(size_t)(c0 + ty + i) * R + r0 + tx] = tl[tx][ty + i];
}

// ---------------- LSTM h-state init + barrier counter reset -------------------
__global__ void init_states(const float* __restrict__ c0f, const float* __restrict__ c0b) {
    int idx = blockIdx.x * blockDim.x + threadIdx.x;   // B*U = 32768
    if (idx == 0) g_sc = 0;
    int u = idx & (UU - 1);
    g_hFa[idx] = tanhf(c0f[u]);
    g_hBa[idx] = tanhf(c0b[u]);
}

// ---------------- big GEMM: C = AT^T @ B, cp.async 4-stage ring ---------------
__global__ void __launch_bounds__(256) sgemm_nt(
    const float* __restrict__ AT, const float* __restrict__ B, float* __restrict__ C,
    int K, int ldat, int ldb, int ldc) {
    extern __shared__ float smg[];
    float* Asm = smg;                 // 4 stages x 2112 floats
    float* Bsm = smg + 4 * 2112;      // 4 stages x 2112 floats
    int m0 = blockIdx.y * 128, n0 = blockIdx.x * 128;
    int tid = threadIdx.x;
    int tx = tid & 15, ty = tid >> 4;
    uint32_t as0 = (uint32_t)__cvta_generic_to_shared(Asm);
    uint32_t bs0 = (uint32_t)__cvta_generic_to_shared(Bsm);
    int akk = tid >> 5, aoff = (tid & 31) * 4;
    int niter = K >> 4;

    ull acc[4][8];
#pragma unroll
    for (int p = 0; p < 4; p++)
#pragma unroll
        for (int j = 0; j < 8; j++) acc[p][j] = 0ULL;

#define SG_STAGE(st, kk0) do { \
        cp_async16(as0 + (uint32_t)(((st) * 2112 + akk * 132 + aoff) * 4), \
                   AT + (size_t)((kk0) + akk) * ldat + m0 + aoff); \
        cp_async16(as0 + (uint32_t)(((st) * 2112 + (akk + 8) * 132 + aoff) * 4), \
                   AT + (size_t)((kk0) + akk + 8) * ldat + m0 + aoff); \
        cp_async16(bs0 + (uint32_t)(((st) * 2112 + akk * 132 + aoff) * 4), \
                   B + (size_t)((kk0) + akk) * ldb + n0 + aoff); \
        cp_async16(bs0 + (uint32_t)(((st) * 2112 + (akk + 8) * 132 + aoff) * 4), \
                   B + (size_t)((kk0) + akk + 8) * ldb + n0 + aoff); \
    } while (0)

    SG_STAGE(0, 0);  cp_commit();
    SG_STAGE(1, 16); cp_commit();
    SG_STAGE(2, 32); cp_commit();

    for (int i = 0; i < niter; i++) {
        int rem = niter - i;
        if (rem >= 3)      cp_wait<2>();
        else if (rem == 2) cp_wait<1>();
        else               cp_wait<0>();
        __syncthreads();
        const float* Ap = Asm + (i & 3) * 2112;
        const float* Bp = Bsm + (i & 3) * 2112;
#pragma unroll
        for (int kk = 0; kk < 16; kk++) {
            ull ap[4];
#pragma unroll
            for (int q = 0; q < 4; q++)
                ap[q] = *(const ull*)(Ap + kk * 132 + ty * 8 + 2 * q);
            float4 bv0 = *(const float4*)(Bp + kk * 132 + tx * 8);
            float4 bv1 = *(const float4*)(Bp + kk * 132 + tx * 8 + 4);
            ull bd[8] = {dup2(bv0.x), dup2(bv0.y), dup2(bv0.z), dup2(bv0.w),
                         dup2(bv1.x), dup2(bv1.y), dup2(bv1.z), dup2(bv1.w)};
#pragma unroll
            for (int q = 0; q < 4; q++)
#pragma unroll
                for (int j = 0; j < 8; j++) fma2(acc[q][j], ap[q], bd[j]);
        }
        if (i + 3 < niter) { SG_STAGE((i + 3) & 3, (i + 3) * 16); cp_commit(); }
    }
#undef SG_STAGE

#pragma unroll
    for (int q = 0; q < 4; q++) {
        float v0[8], v1[8];
#pragma unroll
        for (int j = 0; j < 8; j++) {
            float2 t = unpack2(acc[q][j]);
            v0[j] = t.x; v1[j] = t.y;
        }
        float* c0 = C + (size_t)(m0 + ty * 8 + 2 * q) * ldc + n0 + tx * 8;
        float* c1 = c0 + ldc;
        *(float4*)c0 = make_float4(v0[0], v0[1], v0[2], v0[3]);
        *(float4*)(c0 + 4) = make_float4(v0[4], v0[5], v0[6], v0[7]);
        *(float4*)c1 = make_float4(v1[0], v1[1], v1[2], v1[3]);
        *(float4*)(c1 + 4) = make_float4(v1[4], v1[5], v1[6], v1[7]);
    }
}

// ---------------- fused recurrence layer (R12 base, fast epilogue) ------------
// hout stored + fenced before arrive; outp/outT stores overlap the barrier
// poll (they are only consumed after this kernel ends).
__global__ void __launch_bounds__(128) lstm_layer(
    const float* __restrict__ preF, const float* __restrict__ preB,
    const float* __restrict__ WpF,  const float* __restrict__ WpB,
    const float* __restrict__ bvF,  const float* __restrict__ bvB,
    const float* __restrict__ c0F,  const float* __restrict__ c0B,
    float* __restrict__ outF, float* __restrict__ outB,
    float* __restrict__ outTF, float* __restrict__ outTB, int ostride) {
    extern __shared__ float sm[];
    float* Wsm = sm;                    // 16384 floats (resident W slice)
    float* Asm = sm + 16384;            // 4 stages x 2304 floats

    int blk = blockIdx.x;
    int dir = blk >> 6;
    int nb  = blk & 63;
    int n0  = nb * 32;

    const float* pre = dir ? preB : preF;
    const float* Wp  = dir ? WpB : WpF;
    const float* bv  = dir ? bvB : bvF;
    const float* c0p = dir ? c0B : c0F;
    float* outp  = dir ? outB : outF;
    float* outT  = dir ? outTB : outTF;
    float* hbuf0 = dir ? g_hBa : g_hFa;
    float* hbuf1 = dir ? g_hBb : g_hFb;

    int tid = threadIdx.x;
    int tx = tid >> 4;            // 0..7 : unit within tile
    int ty = tid & 15;            // 0..15: b-group of 4
    int b0 = ty * 4;
    int u = nb * 8 + tx;

    uint32_t wsb = (uint32_t)__cvta_generic_to_shared(Wsm);
    uint32_t asb = (uint32_t)__cvta_generic_to_shared(Asm);

    // load resident W slice: each thread fills its contiguous 128-float span
#pragma unroll
    for (int j = 0; j < 32; j++) {
        int f = tid * 128 + j * 4;
        int row = f >> 6, col = f & 63;
        cp_async16(wsb + (uint32_t)f * 4, Wp + (size_t)row * 4096 + nb * 64 + col);
    }
    cp_commit();

    float4 bb4 = *(const float4*)(bv + n0 + tx * 4);
    float c0v = c0p[u];
    float cv[4] = {c0v, c0v, c0v, c0v};

    // A staging assignment: permuted rows, stride 36
    int sa_row = tid >> 1, sa_off = (tid & 1) * 16;
    int sa_prow = (sa_row & 3) * 16 + (sa_row >> 2);

    cp_wait<0>();
    __syncthreads();   // W resident ready

#define LSA(st, k0) do { \
        _Pragma("unroll") \
        for (int j = 0; j < 4; j++) \
            cp_async16(asb + (uint32_t)((((st) * 2304) + sa_prow * 36 + sa_off + j * 4) * 4), \
                       hin + sa_row * UU + (k0) + sa_off + j * 4); \
    } while (0)

    for (int s = 0; s < T_LEN; s++) {
        int t = dir ? (T_LEN - 1 - s) : s;
        const float* hin = (s & 1) ? hbuf1 : hbuf0;
        float* hout      = (s & 1) ? hbuf0 : hbuf1;

        // per-step pre loads (latency hides under staging + k-loop)
        float4 pv[4];
#pragma unroll
        for (int r = 0; r < 4; r++)
            pv[r] = *(const float4*)(pre + ((size_t)t * BB + b0 + r) * G4 + n0 + tx * 4);

        LSA(0, 0);  cp_commit();
        LSA(1, 32); cp_commit();
        LSA(2, 64); cp_commit();

        ull acc[4][4];
#pragma unroll
        for (int r = 0; r < 4; r++)
#pragma unroll
            for (int j = 0; j < 4; j++) acc[r][j] = 0ULL;

        for (int i = 0; i < 16; i++) {
            if (i < 13)      cp_wait<2>();
            else if (i < 15) cp_wait<1>();
            else             cp_wait<0>();
            __syncthreads();
            const float* Ap = Asm + (i & 3) * 2304;
            const float* Bp = Wsm + i * 1024;
#pragma unroll
            for (int kk4 = 0; kk4 < 8; kk4++) {
                ulonglong2 a2[4];
#pragma unroll
                for (int r = 0; r < 4; r++)
                    a2[r] = *(const ulonglong2*)(Ap + (r * 16 + ty) * 36 + kk4 * 4);
#pragma unroll
                for (int h = 0; h < 2; h++) {
                    int kk2 = kk4 * 2 + h;
                    ulonglong2 w01 = *(const ulonglong2*)(Bp + kk2 * 64 + tx * 4);
                    ulonglong2 w23 = *(const ulonglong2*)(Bp + kk2 * 64 + 32 + tx * 4);
#pragma unroll
                    for (int r = 0; r < 4; r++) {
                        ull a = h ? a2[r].y : a2[r].x;
                        fma2(acc[r][0], a, w01.x);
                        fma2(acc[r][1], a, w01.y);
                        fma2(acc[r][2], a, w23.x);
                        fma2(acc[r][3], a, w23.y);
                    }
                }
            }
            if (i + 3 < 16) { LSA((i + 3) & 3, (i + 3) * 32); cp_commit(); }
        }

        // epilogue: gates + state update; hout first (cross-CTA critical path)
        float hv[4];
#pragma unroll
        for (int r = 0; r < 4; r++) {
            int b = b0 + r;
            float2 e0 = unpack2(acc[r][0]);
            float2 e1 = unpack2(acc[r][1]);
            float2 e2 = unpack2(acc[r][2]);
            float2 e3 = unpack2(acc[r][3]);
            float gi = e0.x + e0.y + pv[r].x + bb4.x;
            float gf = e1.x + e1.y + pv[r].y + bb4.y;
            float go = e2.x + e2.y + pv[r].z + bb4.z;
            float gg = e3.x + e3.y + pv[r].w + bb4.w;
            float ig = fsig(gi);
            float fg = fsig(gf);
            float og = fsig(go);
            float gt = ftanh_f(gg);
            float c = fg * cv[r] + ig * gt;
            float h = og * ftanh_f(c);
            cv[r] = c;
            hv[r] = h;
            hout[b * UU + u] = h;
        }

        if (s + 1 < T_LEN) {
            __syncthreads();
            asm volatile("fence.acq_rel.gpu;" ::: "memory");
            if (tid == 0)
                asm volatile("red.release.gpu.add.u32 [%0], 1;" :: "l"(&g_sc) : "memory");
            // overlapped output stores (consumed only after kernel end)
#pragma unroll
            for (int r = 0; r < 4; r++) {
                int b = b0 + r;
                outp[((size_t)t * BB + b) * ostride + u] = hv[r];
                if (outT) outT[(size_t)u * MTOT + t * BB + b] = hv[r];
            }
            if (tid == 0) {
                unsigned target = (unsigned)(NCTA * (s + 1));
                unsigned x;
                do {
                    asm volatile("ld.acquire.gpu.u32 %0, [%1];" : "=r"(x) : "l"(&g_sc) : "memory");
                } while (x < target);
            }
            __syncthreads();
        } else {
#pragma unroll
            for (int r = 0; r < 4; r++) {
                int b = b0 + r;
                outp[((size_t)t * BB + b) * ostride + u] = hv[r];
                if (outT) outT[(size_t)u * MTOT + t * BB + b] = hv[r];
            }
        }
    }
#undef LSA
}

// ---------------- span feature gather ----------------------------------------
__global__ void build_hi(const int* __restrict__ sl, const int* __restrict__ sr,
                         const int* __restrict__ ll, const int* __restrict__ lr) {
    int idx = blockIdx.x * blockDim.x + threadIdx.x;
    const int NS = BB * 4 * 2048;
    int b, s, c, le, ri;
    float* dst;
    if (idx < NS) {
        b = idx / (4 * 2048); int r = idx - b * (4 * 2048);
        s = r / 2048; c = r - s * 2048;
        le = sl[b * 4 + s]; ri = sr[b * 4 + s];
        dst = g_hi_s + (size_t)b * 8192 + s * 2048 + c;
    } else {
        int j = idx - NS;
        b = j / (3 * 2048); int r = j - b * (3 * 2048);
        s = r / 2048; c = r - s * 2048;
        le = ll[b * 3 + s]; ri = lr[b * 3 + s];
        dst = g_hi_l + (size_t)b * 6144 + s * 2048 + c;
    }
    float v;
    if (c < 512) {
        v = g_in2[((size_t)ri * BB + b) * 1024 + c] - g_in2[((size_t)(le - 1) * BB + b) * 1024 + c];
    } else if (c < 1024) {
        int u = c - 512;
        v = g_fwd2[((size_t)ri * BB + b) * UU + u] - g_fwd2[((size_t)(le - 1) * BB + b) * UU + u];
    } else if (c < 1536) {
        int u = c - 1024;
        v = g_in2[((size_t)le * BB + b) * 1024 + 512 + u] - g_in2[((size_t)(ri + 1) * BB + b) * 1024 + 512 + u];
    } else {
        int u = c - 1536;
        v = g_back2[((size_t)le * BB + b) * UU + u] - g_back2[((size_t)(ri + 1) * BB + b) * UU + u];
    }
    *dst = v;
}

// ---------------- span hidden GEMM: M=64, split-K -----------------------------
__global__ void __launch_bounds__(256) span_gemm(
    const float* __restrict__ A, int lda, const float* __restrict__ B,
    float* __restrict__ Cpart) {
    __shared__ float AsT[16][68];
    __shared__ float Bs[16][68];
    int n0 = blockIdx.x * 64;
    int kbase = blockIdx.y * 512;
    int tid = threadIdx.x;
    int tx = tid & 15, ty = tid >> 4;
    float acc[4][4] = {{0}};
    int ab = tid >> 2, aseg = (tid & 3) * 4;
    int bkk = tid >> 4, bnn = (tid & 15) * 4;
    for (int k0 = kbase; k0 < kbase + 512; k0 += 16) {
        float4 av = *(const float4*)(A + (size_t)ab * lda + k0 + aseg);
        float4 wv = *(const float4*)(B + (size_t)(k0 + bkk) * HD + n0 + bnn);
        __syncthreads();
        AsT[aseg + 0][ab] = av.x; AsT[aseg + 1][ab] = av.y;
        AsT[aseg + 2][ab] = av.z; AsT[aseg + 3][ab] = av.w;
        *(float4*)&Bs[bkk][bnn] = wv;
        __syncthreads();
#pragma unroll
        for (int kk = 0; kk < 16; kk++) {
            float4 a = *(float4*)&AsT[kk][ty * 4];
            float4 w = *(float4*)&Bs[kk][tx * 4];
            float aa[4] = {a.x, a.y, a.z, a.w};
            float ww[4] = {w.x, w.y, w.z, w.w};
#pragma unroll
            for (int i = 0; i < 4; i++)
#pragma unroll
                for (int j = 0; j < 4; j++) acc[i][j] += aa[i] * ww[j];
        }
    }
#pragma unroll
    for (int i = 0; i < 4; i++) {
        int b = ty * 4 + i;
        float4 v = {acc[i][0], acc[i][1], acc[i][2], acc[i][3]};
        *(float4*)(Cpart + ((size_t)blockIdx.y * BB + b) * HD + n0 + tx * 4) = v;
    }
}

__global__ void reduce_relu(const float* __restrict__ part, int nch,
                            const float* __restrict__ bias, float* __restrict__ outh) {
    int idx = blockIdx.x * blockDim.x + threadIdx.x;
    int n = idx & (HD - 1);
    float s = bias[n];
    for (int ch = 0; ch < nch; ch++) s += part[(size_t)ch * BB * HD + idx];
    outh[idx] = fmaxf(s, 0.f);
}

// ---------------- output heads ------------------------------------------------
__global__ void out_heads(const float* __restrict__ soW, const float* __restrict__ sob,
                          const float* __restrict__ loW, const float* __restrict__ lob,
                          float* __restrict__ out) {
    __shared__ float s1[HD], s2[HD];
    int b = blockIdx.x, tid = threadIdx.x;
    for (int i = tid; i < HD; i += blockDim.x) {
        s1[i] = g_hs[b * HD + i];
        s2[i] = g_hl[b * HD + i];
    }
    __syncthreads();
    if (tid < 2) {
        float s = sob[tid];
        for (int k = 0; k < HD; k++) s += s1[k] * soW[k * 2 + tid];
        out[b * 2 + tid] = s;
    } else if (tid < 34) {
        int j = tid - 2;
        float s = lob[j];
        for (int k = 0; k < HD; k++) s += s2[k] * loW[k * 32 + j];
        out[128 + b * 32 + j] = s;
    }
}

// ---------------- host driver --------------------------------------------------
static float* sym(const void* symbol) {
    void* p = nullptr;
    cudaGetSymbolAddress(&p, symbol);
    return (float*)p;
}

extern "C" void kernel_launch(void* const* d_in, const int* in_sizes, int n_in,
                              void* d_out, int out_size) {
    const float* word_emb = (const float*)d_in[0];
    const float* tag_emb  = (const float*)d_in[1];
    const float* l1f_W = (const float*)d_in[2];
    const float* l1f_b = (const float*)d_in[3];
    const float* l1f_c0 = (const float*)d_in[4];
    const float* l1b_W = (const float*)d_in[5];
    const float* l1b_b = (const float*)d_in[6];
    const float* l1b_c0 = (const float*)d_in[7];
    const float* l2f_W = (const float*)d_in[8];
    const float* l2f_b = (const float*)d_in[9];
    const float* l2f_c0 = (const float*)d_in[10];
    const float* l2b_W = (const float*)d_in[11];
    const float* l2b_b = (const float*)d_in[12];
    const float* l2b_c0 = (const float*)d_in[13];
    const float* sh_W = (const float*)d_in[14];
    const float* sh_b = (const float*)d_in[15];
    const float* so_W = (const float*)d_in[16];
    const float* so_b = (const float*)d_in[17];
    const float* lh_W = (const float*)d_in[18];
    const float* lh_b = (const float*)d_in[19];
    const float* lo_W = (const float*)d_in[20];
    const float* lo_b = (const float*)d_in[21];
    const int* word_inds = (const int*)d_in[22];
    const int* tag_inds  = (const int*)d_in[23];
    const int* s_lefts  = (const int*)d_in[24];
    const int* s_rights = (const int*)d_in[25];
    const int* l_lefts  = (const int*)d_in[26];
    const int* l_rights = (const int*)d_in[27];
    float* out = (float*)d_out;

    float* p_sent  = sym(g_sent);
    float* p_sentT = sym(g_sentT);
    float* p_preF  = sym(g_preF);
    float* p_preB  = sym(g_preB);
    float* p_in2   = sym(g_in2);
    float* p_in2T  = sym(g_in2T);
    float* p_fwd2  = sym(g_fwd2);
    float* p_back2 = sym(g_back2);
    float* p_Wx1f = sym(g_Wx1f); float* p_Wx1b = sym(g_Wx1b);
    float* p_Wh1f = sym(g_Wh1f); float* p_Wh1b = sym(g_Wh1b);
    float* p_Wx2f = sym(g_Wx2f); float* p_Wx2b = sym(g_Wx2b);
    float* p_Wh2f = sym(g_Wh2f); float* p_Wh2b = sym(g_Wh2b);
    float* p_bv1f = sym(g_bv1f); float* p_bv1b = sym(g_bv1b);
    float* p_bv2f = sym(g_bv2f); float* p_bv2b = sym(g_bv2b);
    float* p_hi_s = sym(g_hi_s); float* p_hi_l = sym(g_hi_l);
    float* p_part_s = sym(g_part_s); float* p_part_l = sym(g_part_l);
    float* p_hs = sym(g_hs); float* p_hl = sym(g_hl);

    const int LSTM_SMEM = (16384 + 4 * 2304) * 4;   // 102,400 B
    const int SG_SMEM   = (8 * 2112) * 4;           // 67,584 B
    static int smem_set = 0;
    if (!smem_set) {
        cudaFuncSetAttribute(lstm_layer, cudaFuncAttributeMaxDynamicSharedMemorySize,
                             LSTM_SMEM);
        cudaFuncSetAttribute(sgemm_nt, cudaFuncAttributeMaxDynamicSharedMemorySize,
                             SG_SMEM);
        smem_set = 1;
    }

    // 1) pack weights
    pack_lstm<<<2048, 256>>>(l1f_W, l1f_b, p_Wx1f, p_Wh1f, p_bv1f, SENT_D);
    pack_lstm<<<2048, 256>>>(l1b_W, l1b_b, p_Wx1b, p_Wh1b, p_bv1b, SENT_D);
    pack_lstm<<<4096, 256>>>(l2f_W, l2f_b, p_Wx2f, p_Wh2f, p_bv2f, 1024);
    pack_lstm<<<4096, 256>>>(l2b_W, l2b_b, p_Wx2b, p_Wh2b, p_bv2b, 1024);

    // 2) embeddings + transpose for GEMM A operand
    embed_kernel<<<(MTOT * SENT_D) / 256, 256>>>(word_emb, tag_emb, word_inds, tag_inds);
    transpose32<<<dim3(SENT_D / 32, MTOT / 32), dim3(32, 8)>>>(p_sent, p_sentT, MTOT, SENT_D);

    // 3) layer-1 input projections (16384 x 320 x 2048)
    dim3 gpre(G4 / 128, MTOT / 128);
    sgemm_nt<<<gpre, 256, SG_SMEM>>>(p_sentT, p_Wx1f, p_preF, SENT_D, MTOT, G4, G4);
    sgemm_nt<<<gpre, 256, SG_SMEM>>>(p_sentT, p_Wx1b, p_preB, SENT_D, MTOT, G4, G4);

    // 4) layer-1 recurrence: ONE fused persistent launch
    init_states<<<(BB * UU) / 256, 256>>>(l1f_c0, l1b_c0);
    lstm_layer<<<NCTA, 128, LSTM_SMEM>>>(
        p_preF, p_preB, p_Wh1f, p_Wh1b, p_bv1f, p_bv1b, l1f_c0, l1b_c0,
        p_in2, p_in2 + 512, p_in2T, p_in2T + (size_t)512 * MTOT, 1024);

    // 5) layer-2 input projections (16384 x 1024 x 2048)
    sgemm_nt<<<gpre, 256, SG_SMEM>>>(p_in2T, p_Wx2f, p_preF, 1024, MTOT, G4, G4);
    sgemm_nt<<<gpre, 256, SG_SMEM>>>(p_in2T, p_Wx2b, p_preB, 1024, MTOT, G4, G4);

    // 6) layer-2 recurrence
    init_states<<<(BB * UU) / 256, 256>>>(l2f_c0, l2b_c0);
    lstm_layer<<<NCTA, 128, LSTM_SMEM>>>(
        p_preF, p_preB, p_Wh2f, p_Wh2b, p_bv2f, p_bv2b, l2f_c0, l2b_c0,
        p_fwd2, p_back2, (float*)nullptr, (float*)nullptr, UU);

    // 7) span features
    build_hi<<<(BB * 7 * 2048) / 256, 256>>>(s_lefts, s_rights, l_lefts, l_rights);

    // 8) span hidden layers
    span_gemm<<<dim3(HD / 64, 16), 256>>>(p_hi_s, 8192, sh_W, p_part_s);
    span_gemm<<<dim3(HD / 64, 12), 256>>>(p_hi_l, 6144, lh_W, p_part_l);
    reduce_relu<<<(BB * HD) / 256, 256>>>(p_part_s, 16, sh_b, p_hs);
    reduce_relu<<<(BB * HD) / 256, 256>>>(p_part_l, 12, lh_b, p_hl);

    // 9) output heads
    out_heads<<<BB, 128>>>(so_W, so_b, lo_W, lo_b, out);
}